// round 6
// baseline (speedup 1.0000x reference)
#include <cuda_runtime.h>
#include <math.h>
#include <stdint.h>

#define B_   4
#define T_   4096
#define C_   1024
#define H_   16
#define CS_  128
#define D_   64
#define NC_  32
#define EPS_ 1e-5f

// ---------------- scratch (device globals; no allocations allowed) ----------------
__device__ float g_pm  [(size_t)16384 * 1024];   // pm [m,n]
__device__ float g_lcm [(size_t)262144 * 64];    // per-chunk cumsum [blk,s,d]
__device__ float g_csum[2048 * 64];
__device__ float g_ncar[2048 * 64];
__device__ float g_comb[(size_t)262144 * 128];   // first gmc [blk,s,d], then comb rows
__device__ float g_obuf[(size_t)16384 * 1024];   // mlp out scattered (tf32-rounded)
__device__ float g_pbuf[(size_t)16384 * 1024];   // proj out pre-LN
__device__ float g_xr  [(size_t)16384 * 1024];   // x tf32-rounded
__device__ float g_wmT [(size_t)1024 * 1024];    // W^T [N,K] tf32-rounded
__device__ float g_wgT [(size_t)1024 * 1024];
__device__ float g_wpT [(size_t)1024 * 1024];
__device__ float g_w1T [128 * 128];
__device__ float g_w2T [64 * 128];

__device__ __forceinline__ float warpSum(float v) {
#pragma unroll
    for (int o = 16; o > 0; o >>= 1) v += __shfl_xor_sync(0xffffffffu, v, o);
    return v;
}
__device__ __forceinline__ float tf32r(float f) {
    uint32_t u;
    asm("cvt.rna.tf32.f32 %0, %1;" : "=r"(u) : "f"(f));
    return __uint_as_float(u);
}
__device__ __forceinline__ uint32_t smem_u32(const void* p) {
    uint32_t a;
    asm("{ .reg .u64 t; cvta.to.shared.u64 t, %1; cvt.u32.u64 %0, t; }" : "=r"(a) : "l"(p));
    return a;
}
__device__ __forceinline__ void cp16(uint32_t dst, const void* src) {
    asm volatile("cp.async.cg.shared.global [%0], [%1], 16;" :: "r"(dst), "l"(src));
}
#define LDSM4(r0, r1, r2, r3, addr) \
    asm volatile("ldmatrix.sync.aligned.m8n8.x4.shared.b16 {%0,%1,%2,%3}, [%4];" \
        : "=r"(r0), "=r"(r1), "=r"(r2), "=r"(r3) : "r"(addr))
__device__ __forceinline__ void mma_tf32(float c[4],
                                         uint32_t a0, uint32_t a1, uint32_t a2, uint32_t a3,
                                         uint32_t b0, uint32_t b1) {
    asm volatile(
        "mma.sync.aligned.m16n8k8.row.col.f32.tf32.tf32.f32 "
        "{%0,%1,%2,%3}, {%4,%5,%6,%7}, {%8,%9}, {%0,%1,%2,%3};"
        : "+f"(c[0]), "+f"(c[1]), "+f"(c[2]), "+f"(c[3])
        : "r"(a0), "r"(a1), "r"(a2), "r"(a3), "r"(b0), "r"(b1));
}

// stage ROWS x 32-float tile (128B rows, XOR-granule swizzle) via cp.async, NTH threads
template <int ROWS, int NTH>
__device__ __forceinline__ void stage_tile(uint32_t sdst, const float* __restrict__ gsrc,
                                           int K, int tid) {
#pragma unroll
    for (int i = 0; i < ROWS * 8 / NTH; i++) {
        const int c = i * NTH + tid;
        const int m = c >> 3, g4 = c & 7;
        cp16(sdst + (uint32_t)(m * 128 + ((g4 ^ (m & 7)) << 4)),
             gsrc + (size_t)m * K + g4 * 4);
    }
}

// ============ TF32 GEMM: 128x256x32 CTA tile, 512 thr, 3-stage pipeline ============
// A[M,K] row-major tf32-rounded fp32, Bt[N,K] row-major. Warp grid 4(M)x4(N), warp 32x64.
// EPI 0: C = acc+bias. EPI 1: C2(chunked [blk,s,d]) = sigmoid(acc+bias) * C(pm).
template <int EPI>
__global__ __launch_bounds__(512, 1)
void tgemm3(int M, int N, int K,
            const float* __restrict__ A,
            const float* __restrict__ Bt,
            const float* __restrict__ bias,
            float* __restrict__ C,
            float* __restrict__ C2)
{
    constexpr int NT2 = 8, NPAIR = 4;          // warp N = 64
    constexpr int STG = 48 * 1024;             // per-stage: A 16KB + B 32KB

    extern __shared__ char smem[];
    const uint32_t sb = smem_u32(smem);

    const int tid = threadIdx.x, wid = tid >> 5, lane = tid & 31;
    const int wy = wid >> 2, wx = wid & 3;
    const int gid = lane >> 2, tig = lane & 3;
    const int lrow = lane & 15, lgh = lane >> 4;

    const int crow = blockIdx.y * 128, ccol = blockIdx.x * 256;
    const float* Ag = A + (size_t)crow * K;
    const float* Bg = Bt + (size_t)ccol * K;

    float acc[2][NT2][4];
#pragma unroll
    for (int q = 0; q < 2; q++)
#pragma unroll
        for (int nt = 0; nt < NT2; nt++)
#pragma unroll
            for (int e = 0; e < 4; e++) acc[q][nt][e] = 0.f;

    const int nT = K / 32;

    // prologue: stage k-tiles 0, 1
#pragma unroll
    for (int s = 0; s < 2; s++) {
        stage_tile<128, 512>(sb + s * STG, Ag + s * 32, K, tid);
        stage_tile<256, 512>(sb + s * STG + 16384, Bg + s * 32, K, tid);
        asm volatile("cp.async.commit_group;");
    }

    for (int t = 0; t < nT; t++) {
        if (t < nT - 1) asm volatile("cp.async.wait_group 1;" ::: "memory");
        else            asm volatile("cp.async.wait_group 0;" ::: "memory");
        __syncthreads();
        if (t + 2 < nT) {
            const int slot = (t + 2) % 3;
            stage_tile<128, 512>(sb + slot * STG, Ag + (t + 2) * 32, K, tid);
            stage_tile<256, 512>(sb + slot * STG + 16384, Bg + (t + 2) * 32, K, tid);
            asm volatile("cp.async.commit_group;");
        }
        const uint32_t aBase = sb + (t % 3) * STG;
        const uint32_t bBase = aBase + 16384;
#pragma unroll
        for (int kk2 = 0; kk2 < 8; kk2 += 2) {
            uint32_t a[2][4];
#pragma unroll
            for (int q = 0; q < 2; q++) {
                const int row = wy * 32 + q * 16 + lrow;
                LDSM4(a[q][0], a[q][1], a[q][2], a[q][3],
                      aBase + row * 128 + (((kk2 + lgh) ^ (row & 7)) << 4));
            }
            uint32_t bfr[NT2][2];
#pragma unroll
            for (int p = 0; p < NPAIR; p++) {
                const int row = wx * 64 + p * 16 + lrow;
                uint32_t r0, r1, r2, r3;
                LDSM4(r0, r1, r2, r3, bBase + row * 128 + (((kk2 + lgh) ^ (row & 7)) << 4));
                bfr[2 * p][0] = r0; bfr[2 * p + 1][0] = r1;
                bfr[2 * p][1] = r2; bfr[2 * p + 1][1] = r3;
            }
#pragma unroll
            for (int q = 0; q < 2; q++)
#pragma unroll
                for (int nt = 0; nt < NT2; nt++)
                    mma_tf32(acc[q][nt], a[q][0], a[q][1], a[q][2], a[q][3],
                             bfr[nt][0], bfr[nt][1]);
        }
    }

    // epilogue
#pragma unroll
    for (int q = 0; q < 2; q++) {
#pragma unroll
        for (int nt = 0; nt < NT2; nt++) {
#pragma unroll
            for (int eh = 0; eh < 2; eh++) {
                const int m = crow + wy * 32 + q * 16 + gid + eh * 8;
                const int n = ccol + wx * 64 + nt * 8 + tig * 2;
                float2 v;
                v.x = acc[q][nt][eh * 2 + 0] + bias[n];
                v.y = acc[q][nt][eh * 2 + 1] + bias[n + 1];
                if (EPI == 1) {
                    const float2 old = *reinterpret_cast<const float2*>(C + (size_t)m * N + n);
                    v.x = old.x / (1.f + __expf(-v.x));
                    v.y = old.y / (1.f + __expf(-v.y));
                    const int s = m & 127, ch = (m >> 7) & 31, h = n >> 6, b = m >> 12;
                    const int d = n & 63;
                    const size_t idx = ((((size_t)(b * 16 + h) * 32 + ch) * 128 + s) * 64) + d;
                    *reinterpret_cast<float2*>(C2 + idx) = v;
                } else {
                    *reinterpret_cast<float2*>(C + (size_t)m * N + n) = v;
                }
            }
        }
    }
}

// ============ fused MLP: comb -> gelu(comb@W1+b1) in smem -> @W2+b2 -> scatter ============
// grid 2048 (row blocks of 128), 256 threads (8 warps). A pipeline = 3-slot ring (race-free).
__global__ __launch_bounds__(256, 1)
void mlp_fused(const float* __restrict__ comb,
               const float* __restrict__ w1T, const float* __restrict__ w2T,
               const float* __restrict__ b1, const float* __restrict__ b2,
               float* __restrict__ obuf)
{
    extern __shared__ char smem[];
    const uint32_t sb  = smem_u32(smem);
    const uint32_t sW1 = sb;                 // 4 chunks x 16KB = 64KB
    const uint32_t sW2 = sb + 65536;         // 4 chunks x  8KB = 32KB
    const uint32_t sH  = sb + 98304;         // 4 chunks x 16KB = 64KB
    const uint32_t sA  = sb + 163840;        // 3 slots  x 16KB = 48KB

    const int tid = threadIdx.x, wid = tid >> 5, lane = tid & 31;
    const int wy = wid >> 2, wx = wid & 3;               // 2 x 4
    const int gid = lane >> 2, tig = lane & 3;
    const int lrow = lane & 15, lgh = lane >> 4;
    const int crow = blockIdx.x * 128;

    // stage W1 (all 4 k-chunks) + W2 + A chunk 0 in group 0
#pragma unroll
    for (int i = 0; i < 16; i++) {
        const int c = i * 256 + tid;
        const int kt = c >> 10, rem = c & 1023, n = rem >> 3, g4 = rem & 7;
        cp16(sW1 + kt * 16384 + n * 128 + ((g4 ^ (n & 7)) << 4),
             w1T + (size_t)n * 128 + kt * 32 + g4 * 4);
    }
#pragma unroll
    for (int i = 0; i < 8; i++) {
        const int c = i * 256 + tid;
        const int kt = c >> 9, rem = c & 511, n = rem >> 3, g4 = rem & 7;
        cp16(sW2 + kt * 8192 + n * 128 + ((g4 ^ (n & 7)) << 4),
             w2T + (size_t)n * 128 + kt * 32 + g4 * 4);
    }
    stage_tile<128, 256>(sA, comb + (size_t)crow * 128, 128, tid);
    asm volatile("cp.async.commit_group;");
    // A chunk 1 in group 1
    stage_tile<128, 256>(sA + 16384, comb + (size_t)crow * 128 + 32, 128, tid);
    asm volatile("cp.async.commit_group;");

    float acc1[4][4][4];
#pragma unroll
    for (int q = 0; q < 4; q++)
#pragma unroll
        for (int nt = 0; nt < 4; nt++)
#pragma unroll
            for (int e = 0; e < 4; e++) acc1[q][nt][e] = 0.f;

    // GEMM1: 128x128x128, warp tile 64x32, A in 3-slot ring
    for (int kt = 0; kt < 4; kt++) {
        if (kt < 3) asm volatile("cp.async.wait_group 1;" ::: "memory");
        else        asm volatile("cp.async.wait_group 0;" ::: "memory");
        __syncthreads();
        if (kt + 2 < 4) {
            stage_tile<128, 256>(sA + ((kt + 2) % 3) * 16384,
                                 comb + (size_t)crow * 128 + (kt + 2) * 32, 128, tid);
            asm volatile("cp.async.commit_group;");
        }
        const uint32_t aBase = sA + (kt % 3) * 16384;
        const uint32_t bBase = sW1 + kt * 16384;
#pragma unroll
        for (int kk2 = 0; kk2 < 8; kk2 += 2) {
            uint32_t a[4][4];
#pragma unroll
            for (int q = 0; q < 4; q++) {
                const int row = wy * 64 + q * 16 + lrow;
                LDSM4(a[q][0], a[q][1], a[q][2], a[q][3],
                      aBase + row * 128 + (((kk2 + lgh) ^ (row & 7)) << 4));
            }
            uint32_t bfr[4][2];
#pragma unroll
            for (int p = 0; p < 2; p++) {
                const int row = wx * 32 + p * 16 + lrow;
                uint32_t r0, r1, r2, r3;
                LDSM4(r0, r1, r2, r3, bBase + row * 128 + (((kk2 + lgh) ^ (row & 7)) << 4));
                bfr[2 * p][0] = r0; bfr[2 * p + 1][0] = r1;
                bfr[2 * p][1] = r2; bfr[2 * p + 1][1] = r3;
            }
#pragma unroll
            for (int q = 0; q < 4; q++)
#pragma unroll
                for (int nt = 0; nt < 4; nt++)
                    mma_tf32(acc1[q][nt], a[q][0], a[q][1], a[q][2], a[q][3],
                             bfr[nt][0], bfr[nt][1]);
        }
        __syncthreads();
    }

    // gelu + tf32 round -> sH (A-operand layout, 4 k-chunks of 32)
#pragma unroll
    for (int q = 0; q < 4; q++) {
#pragma unroll
        for (int nt = 0; nt < 4; nt++) {
#pragma unroll
            for (int eh = 0; eh < 2; eh++) {
                const int m = wy * 64 + q * 16 + gid + eh * 8;
                const int n = wx * 32 + nt * 8 + tig * 2;
                float2 v;
                v.x = acc1[q][nt][eh * 2 + 0] + b1[n];
                v.y = acc1[q][nt][eh * 2 + 1] + b1[n + 1];
                v.x = tf32r(0.5f * v.x * (1.f + erff(v.x * 0.70710678118654752440f)));
                v.y = tf32r(0.5f * v.y * (1.f + erff(v.y * 0.70710678118654752440f)));
                const int kt = n >> 5, g4 = (n & 31) >> 2;
                const uint32_t ad = sH + kt * 16384 + m * 128 + ((g4 ^ (m & 7)) << 4) + (n & 3) * 4;
                asm volatile("st.shared.v2.f32 [%0], {%1,%2};" :: "r"(ad), "f"(v.x), "f"(v.y));
            }
        }
    }
    __syncthreads();

    // GEMM2: 128x64x128, warp tile 64x16
    float acc2[4][2][4];
#pragma unroll
    for (int q = 0; q < 4; q++)
#pragma unroll
        for (int nt = 0; nt < 2; nt++)
#pragma unroll
            for (int e = 0; e < 4; e++) acc2[q][nt][e] = 0.f;

#pragma unroll 1
    for (int kt = 0; kt < 4; kt++) {
        const uint32_t aBase = sH + kt * 16384;
        const uint32_t bBase = sW2 + kt * 8192;
#pragma unroll
        for (int kk2 = 0; kk2 < 8; kk2 += 2) {
            uint32_t a[4][4];
#pragma unroll
            for (int q = 0; q < 4; q++) {
                const int row = wy * 64 + q * 16 + lrow;
                LDSM4(a[q][0], a[q][1], a[q][2], a[q][3],
                      aBase + row * 128 + (((kk2 + lgh) ^ (row & 7)) << 4));
            }
            uint32_t bfr[2][2];
            {
                const int row = wx * 16 + lrow;
                uint32_t r0, r1, r2, r3;
                LDSM4(r0, r1, r2, r3, bBase + row * 128 + (((kk2 + lgh) ^ (row & 7)) << 4));
                bfr[0][0] = r0; bfr[1][0] = r1; bfr[0][1] = r2; bfr[1][1] = r3;
            }
#pragma unroll
            for (int q = 0; q < 4; q++)
#pragma unroll
                for (int nt = 0; nt < 2; nt++)
                    mma_tf32(acc2[q][nt], a[q][0], a[q][1], a[q][2], a[q][3],
                             bfr[nt][0], bfr[nt][1]);
        }
    }

    // epilogue: bias + tf32 round, scatter to (b,t,c)
#pragma unroll
    for (int q = 0; q < 4; q++) {
#pragma unroll
        for (int nt = 0; nt < 2; nt++) {
#pragma unroll
            for (int eh = 0; eh < 2; eh++) {
                const int mm = crow + wy * 64 + q * 16 + gid + eh * 8;
                const int n = wx * 16 + nt * 8 + tig * 2;
                float2 v;
                v.x = tf32r(acc2[q][nt][eh * 2 + 0] + b2[n]);
                v.y = tf32r(acc2[q][nt][eh * 2 + 1] + b2[n + 1]);
                const int s = mm & 127, ch = (mm >> 7) & 31, h = (mm >> 12) & 15, b = mm >> 16;
                const size_t oidx = (((size_t)b * T_) + ch * CS_ + s) * C_ + h * D_ + n;
                *reinterpret_cast<float2*>(obuf + oidx) = v;
            }
        }
    }
}

// ============================ converts ============================
__global__ __launch_bounds__(256)
void cvt_round_kernel(const float4* __restrict__ src, float4* __restrict__ dst, int n4)
{
    const int i = blockIdx.x * blockDim.x + threadIdx.x;
    if (i >= n4) return;
    float4 v = src[i];
    v.x = tf32r(v.x); v.y = tf32r(v.y); v.z = tf32r(v.z); v.w = tf32r(v.w);
    dst[i] = v;
}

__global__ void cvt_wt_kernel(const float* __restrict__ W, float* __restrict__ Wt,
                              int Kd, int Nd)
{
    __shared__ float tile[32][33];
    const int k0 = blockIdx.y * 32, n0 = blockIdx.x * 32;
    const int tx = threadIdx.x, ty = threadIdx.y;
#pragma unroll
    for (int j = 0; j < 32; j += 8)
        tile[ty + j][tx] = W[(size_t)(k0 + ty + j) * Nd + n0 + tx];
    __syncthreads();
#pragma unroll
    for (int j = 0; j < 32; j += 8)
        Wt[(size_t)(n0 + ty + j) * Kd + k0 + tx] = tf32r(tile[tx][ty + j]);
}

// ---------------- per-chunk cumsum + chunk sums (contiguous gmc layout) ----------------
__global__ void chunk_scan_kernel(const float* __restrict__ gmc,
                                  float* __restrict__ lcm,
                                  float* __restrict__ csum)
{
    const int blk = blockIdx.x;        // 2048
    const int d   = threadIdx.x;       // 64
    const float* src = gmc + (size_t)blk * CS_ * D_ + d;
    float* dst = lcm + (size_t)blk * CS_ * D_ + d;
    float acc = 0.f;
    for (int s = 0; s < CS_; s++) {
        acc += src[(size_t)s * D_];
        dst[(size_t)s * D_] = acc;
    }
    csum[(size_t)blk * D_ + d] = acc;
}

// ---------------- cross-chunk exclusive scan + carry LayerNorm ----------------
__global__ void carry_ln_kernel(const float* __restrict__ csum,
                                const float* __restrict__ g,
                                const float* __restrict__ bb,
                                float* __restrict__ ncar)
{
    const int bh = blockIdx.x;
    const int d  = threadIdx.x;
    const int lane = d & 31, w = d >> 5;
    __shared__ float sh[2];
    const float gd = g[d], bd = bb[d];
    float run = 0.f;
    for (int ch = 0; ch < NC_; ch++) {
        const float carry = run;
        run += csum[(size_t)(bh * NC_ + ch) * D_ + d];
        float s = warpSum(carry);
        if (lane == 0) sh[w] = s;
        __syncthreads();
        const float mean = (sh[0] + sh[1]) * (1.f / 64.f);
        __syncthreads();
        const float df = carry - mean;
        float s2 = warpSum(df * df);
        if (lane == 0) sh[w] = s2;
        __syncthreads();
        const float var = (sh[0] + sh[1]) * (1.f / 64.f);
        __syncthreads();
        ncar[(size_t)(bh * NC_ + ch) * D_ + d] = df * rsqrtf(var + EPS_) * gd + bd;
    }
}

// ---------------- cards (LN over D) + comb = [x_h | cards], tf32-rounded ----------------
__global__ __launch_bounds__(128)
void cards_comb_kernel(const float* __restrict__ x,
                       const float* __restrict__ lcm,
                       const float* __restrict__ ncar,
                       const float* __restrict__ cg,
                       const float* __restrict__ cb,
                       float* __restrict__ comb)
{
    const int blk = blockIdx.x;
    const int s   = threadIdx.x;
    const int ch  = blk % NC_;
    const int h   = (blk / NC_) % H_;
    const int b   = blk / (NC_ * H_);

    __shared__ float ncs[D_], gs[D_], bs[D_];
    if (s < D_) { ncs[s] = ncar[(size_t)blk * D_ + s]; gs[s] = cg[s]; bs[s] = cb[s]; }
    __syncthreads();

    float v[D_];
    if (s == 0) {
#pragma unroll
        for (int d = 0; d < D_; d++) v[d] = ncs[d];
    } else {
        const float4* l4 = reinterpret_cast<const float4*>(
            lcm + ((size_t)blk * CS_ + (s - 1)) * D_);
#pragma unroll
        for (int i = 0; i < D_ / 4; i++) {
            const float4 t = l4[i];
            v[4 * i + 0] = t.x + ncs[4 * i + 0];
            v[4 * i + 1] = t.y + ncs[4 * i + 1];
            v[4 * i + 2] = t.z + ncs[4 * i + 2];
            v[4 * i + 3] = t.w + ncs[4 * i + 3];
        }
    }
    float sum = 0.f;
#pragma unroll
    for (int d = 0; d < D_; d++) sum += v[d];
    const float mean = sum * (1.f / 64.f);
    float sq = 0.f;
#pragma unroll
    for (int d = 0; d < D_; d++) { const float df = v[d] - mean; sq += df * df; }
    const float rs = rsqrtf(sq * (1.f / 64.f) + EPS_);

    const size_t row = (size_t)blk * CS_ + s;
    float4* cout = reinterpret_cast<float4*>(comb + row * 128);
    const float4* xr = reinterpret_cast<const float4*>(
        x + (((size_t)b * T_) + ch * CS_ + s) * C_ + h * D_);
#pragma unroll
    for (int i = 0; i < D_ / 4; i++) {
        float4 t = xr[i];
        t.x = tf32r(t.x); t.y = tf32r(t.y); t.z = tf32r(t.z); t.w = tf32r(t.w);
        cout[i] = t;
    }
#pragma unroll
    for (int i = 0; i < D_ / 4; i++) {
        float4 t;
        t.x = tf32r((v[4 * i + 0] - mean) * rs * gs[4 * i + 0] + bs[4 * i + 0]);
        t.y = tf32r((v[4 * i + 1] - mean) * rs * gs[4 * i + 1] + bs[4 * i + 1]);
        t.z = tf32r((v[4 * i + 2] - mean) * rs * gs[4 * i + 2] + bs[4 * i + 2]);
        t.w = tf32r((v[4 * i + 3] - mean) * rs * gs[4 * i + 3] + bs[4 * i + 3]);
        cout[16 + i] = t;
    }
}

// ---------------- final LayerNorm over C + residual ----------------
__global__ __launch_bounds__(256)
void ln_res_kernel(const float* __restrict__ p, const float* __restrict__ x,
                   const float* __restrict__ g, const float* __restrict__ bb,
                   float* __restrict__ out)
{
    const int row = blockIdx.x;
    const int t   = threadIdx.x;
    const float4 lv = reinterpret_cast<const float4*>(p + (size_t)row * C_)[t];
    float s = lv.x + lv.y + lv.z + lv.w;
    __shared__ float red[8];
    s = warpSum(s);
    if ((t & 31) == 0) red[t >> 5] = s;
    __syncthreads();
    float tot = 0.f;
#pragma unroll
    for (int i = 0; i < 8; i++) tot += red[i];
    const float mean = tot * (1.f / 1024.f);
    __syncthreads();
    const float d0 = lv.x - mean, d1 = lv.y - mean, d2 = lv.z - mean, d3 = lv.w - mean;
    float sq = d0 * d0 + d1 * d1 + d2 * d2 + d3 * d3;
    sq = warpSum(sq);
    if ((t & 31) == 0) red[t >> 5] = sq;
    __syncthreads();
    float v2 = 0.f;
#pragma unroll
    for (int i = 0; i < 8; i++) v2 += red[i];
    const float rs = rsqrtf(v2 * (1.f / 1024.f) + EPS_);
    const float4 xv = reinterpret_cast<const float4*>(x + (size_t)row * C_)[t];
    const float4 gv = reinterpret_cast<const float4*>(g)[t];
    const float4 bv = reinterpret_cast<const float4*>(bb)[t];
    float4 o;
    o.x = xv.x + d0 * rs * gv.x + bv.x;
    o.y = xv.y + d1 * rs * gv.y + bv.y;
    o.z = xv.z + d2 * rs * gv.z + bv.z;
    o.w = xv.w + d3 * rs * gv.w + bv.w;
    reinterpret_cast<float4*>(out + (size_t)row * C_)[t] = o;
}

// ---------------- launch ----------------
extern "C" void kernel_launch(void* const* d_in, const int* in_sizes, int n_in,
                              void* d_out, int out_size)
{
    const float* x       = (const float*)d_in[0];
    const float* mark_W  = (const float*)d_in[1];
    const float* mark_b  = (const float*)d_in[2];
    const float* gate_W  = (const float*)d_in[3];
    const float* gate_b  = (const float*)d_in[4];
    const float* carry_g = (const float*)d_in[5];
    const float* carry_b = (const float*)d_in[6];
    const float* card_g  = (const float*)d_in[7];
    const float* card_b  = (const float*)d_in[8];
    const float* ho1_W   = (const float*)d_in[9];
    const float* ho1_b   = (const float*)d_in[10];
    const float* ho2_W   = (const float*)d_in[11];
    const float* ho2_b   = (const float*)d_in[12];
    const float* proj_W  = (const float*)d_in[13];
    const float* proj_b  = (const float*)d_in[14];
    const float* ln_g    = (const float*)d_in[15];
    const float* ln_b    = (const float*)d_in[16];
    float* out = (float*)d_out;

    static float *pm = nullptr, *lcm, *csum, *ncar, *comb, *obuf, *pbuf;
    static float *xr, *wmT, *wgT, *wpT, *w1T, *w2T;
    if (!pm) {
        cudaGetSymbolAddress((void**)&pm,   g_pm);
        cudaGetSymbolAddress((void**)&lcm,  g_lcm);
        cudaGetSymbolAddress((void**)&csum, g_csum);
        cudaGetSymbolAddress((void**)&ncar, g_ncar);
        cudaGetSymbolAddress((void**)&comb, g_comb);
        cudaGetSymbolAddress((void**)&obuf, g_obuf);
        cudaGetSymbolAddress((void**)&pbuf, g_pbuf);
        cudaGetSymbolAddress((void**)&xr,   g_xr);
        cudaGetSymbolAddress((void**)&wmT,  g_wmT);
        cudaGetSymbolAddress((void**)&wgT,  g_wgT);
        cudaGetSymbolAddress((void**)&wpT,  g_wpT);
        cudaGetSymbolAddress((void**)&w1T,  g_w1T);
        cudaGetSymbolAddress((void**)&w2T,  g_w2T);
        cudaFuncSetAttribute(tgemm3<0>, cudaFuncAttributeMaxDynamicSharedMemorySize, 147456);
        cudaFuncSetAttribute(tgemm3<1>, cudaFuncAttributeMaxDynamicSharedMemorySize, 147456);
        cudaFuncSetAttribute(mlp_fused, cudaFuncAttributeMaxDynamicSharedMemorySize, 212992);
    }

    const int M  = B_ * T_;              // 16384
    const int n4 = M * C_ / 4;

    // pre-round / transpose
    cvt_round_kernel<<<(n4 + 255) / 256, 256>>>((const float4*)x, (float4*)xr, n4);
    cvt_wt_kernel<<<dim3(32, 32), dim3(32, 8)>>>(mark_W, wmT, 1024, 1024);
    cvt_wt_kernel<<<dim3(32, 32), dim3(32, 8)>>>(gate_W, wgT, 1024, 1024);
    cvt_wt_kernel<<<dim3(32, 32), dim3(32, 8)>>>(proj_W, wpT, 1024, 1024);
    cvt_wt_kernel<<<dim3(4, 4),   dim3(32, 8)>>>(ho1_W,  w1T, 128, 128);
    cvt_wt_kernel<<<dim3(2, 4),   dim3(32, 8)>>>(ho2_W,  w2T, 128, 64);

    // pm = x @ mark_W + mark_b
    tgemm3<0><<<dim3(4, 128), 512, 147456>>>(M, C_, C_, xr, wmT, mark_b, pm, nullptr);
    // gmc (chunked) = sigmoid(x @ gate_W + gate_b) * pm   (gmc lives in comb buffer)
    tgemm3<1><<<dim3(4, 128), 512, 147456>>>(M, C_, C_, xr, wgT, gate_b, pm, comb);

    chunk_scan_kernel<<<2048, 64>>>(comb, lcm, csum);
    carry_ln_kernel<<<B_ * H_, 64>>>(csum, carry_g, carry_b, ncar);
    cards_comb_kernel<<<B_ * H_ * NC_, 128>>>(x, lcm, ncar, card_g, card_b, comb);

    // fused MLP: comb -> obuf
    mlp_fused<<<2048, 256, 212992>>>(comb, w1T, w2T, ho1_b, ho2_b, obuf);

    // proj
    tgemm3<0><<<dim3(4, 128), 512, 147456>>>(M, C_, C_, obuf, wpT, proj_b, pbuf, nullptr);

    ln_res_kernel<<<M, 256>>>(pbuf, x, ln_g, ln_b, out);
}

// round 10
// speedup vs baseline: 1.5417x; 1.5417x over previous
#include <cuda_runtime.h>
#include <cuda_fp16.h>
#include <math.h>
#include <stdint.h>

#define B_   4
#define T_   4096
#define C_   1024
#define H_   16
#define CS_  128
#define D_   64
#define NC_  32
#define EPS_ 1e-5f

// ---------------- scratch (device globals; no allocations allowed) ----------------
__device__ float  g_pm  [(size_t)16384 * 1024];   // pm [m,n] fp32
__device__ float  g_scan[(size_t)262144 * 64];    // gmc -> in-place cumsum [blk,s,d] fp32
__device__ float  g_csum[2048 * 64];
__device__ float  g_ncar[2048 * 64];
__device__ float  g_pbuf[(size_t)16384 * 1024];   // proj out pre-LN fp32
__device__ __half g_xh  [(size_t)16384 * 1024];   // x fp16
__device__ __half g_comb[(size_t)262144 * 128];   // [x_h | cards] fp16
__device__ __half g_obuf[(size_t)16384 * 1024];   // mlp out scattered fp16
__device__ __half g_wmT [(size_t)1024 * 1024];    // W^T [N,K] fp16
__device__ __half g_wgT [(size_t)1024 * 1024];
__device__ __half g_wpT [(size_t)1024 * 1024];
__device__ __half g_w1T [128 * 128];
__device__ __half g_w2T [64 * 128];

__device__ __forceinline__ float warpSum(float v) {
#pragma unroll
    for (int o = 16; o > 0; o >>= 1) v += __shfl_xor_sync(0xffffffffu, v, o);
    return v;
}
__device__ __forceinline__ uint32_t smem_u32(const void* p) {
    uint32_t a;
    asm("{ .reg .u64 t; cvta.to.shared.u64 t, %1; cvt.u32.u64 %0, t; }" : "=r"(a) : "l"(p));
    return a;
}
__device__ __forceinline__ void cp16(uint32_t dst, const void* src) {
    asm volatile("cp.async.cg.shared.global [%0], [%1], 16;" :: "r"(dst), "l"(src));
}
#define LDSM4(r0, r1, r2, r3, addr) \
    asm volatile("ldmatrix.sync.aligned.m8n8.x4.shared.b16 {%0,%1,%2,%3}, [%4];" \
        : "=r"(r0), "=r"(r1), "=r"(r2), "=r"(r3) : "r"(addr))
__device__ __forceinline__ void mma_f16(float c[4],
                                        uint32_t a0, uint32_t a1, uint32_t a2, uint32_t a3,
                                        uint32_t b0, uint32_t b1) {
    asm volatile(
        "mma.sync.aligned.m16n8k16.row.col.f32.f16.f16.f32 "
        "{%0,%1,%2,%3}, {%4,%5,%6,%7}, {%8,%9}, {%0,%1,%2,%3};"
        : "+f"(c[0]), "+f"(c[1]), "+f"(c[2]), "+f"(c[3])
        : "r"(a0), "r"(a1), "r"(a2), "r"(a3), "r"(b0), "r"(b1));
}
__device__ __forceinline__ uint32_t h2u(float a, float b) {
    __half2 h = __floats2half2_rn(a, b);
    return *reinterpret_cast<uint32_t*>(&h);
}

// stage ROWS x 64-half tile (128B rows, XOR-granule swizzle) via cp.async; K in halfs
template <int ROWS, int NTH>
__device__ __forceinline__ void stage_tile_h(uint32_t sdst, const __half* __restrict__ gsrc,
                                             int K, int tid) {
#pragma unroll
    for (int i = 0; i < ROWS * 8 / NTH; i++) {
        const int c = i * NTH + tid;
        const int m = c >> 3, g4 = c & 7;
        cp16(sdst + (uint32_t)(m * 128 + ((g4 ^ (m & 7)) << 4)),
             gsrc + (size_t)m * K + g4 * 8);
    }
}

// ============ FP16 GEMM: 128x256x64 CTA k-tile, 512 thr, 3-stage pipeline ============
// A[M,K] half row-major, Bt[N,K] half row-major. Warp grid 4(M)x4(N), warp 32x64.
// EPI 0: C(fp32) = acc+bias. EPI 1: C2(fp32 chunked [blk,s,d]) = sigmoid(acc+bias)*C(pm).
template <int EPI>
__global__ __launch_bounds__(512, 1)
void hgemm(int M, int N, int K,
           const __half* __restrict__ A,
           const __half* __restrict__ Bt,
           const float* __restrict__ bias,
           float* __restrict__ C,
           float* __restrict__ C2)
{
    constexpr int NT2 = 8, NPAIR = 4;          // warp N = 64
    constexpr int STG = 48 * 1024;             // A 16KB + B 32KB per stage

    extern __shared__ char smem[];
    const uint32_t sb = smem_u32(smem);

    const int tid = threadIdx.x, wid = tid >> 5, lane = tid & 31;
    const int wy = wid >> 2, wx = wid & 3;
    const int gid = lane >> 2, tig = lane & 3;
    const int lrow = lane & 15, lgh = lane >> 4;

    const int crow = blockIdx.y * 128, ccol = blockIdx.x * 256;
    const __half* Ag = A + (size_t)crow * K;
    const __half* Bg = Bt + (size_t)ccol * K;

    float acc[2][NT2][4];
#pragma unroll
    for (int q = 0; q < 2; q++)
#pragma unroll
        for (int nt = 0; nt < NT2; nt++)
#pragma unroll
            for (int e = 0; e < 4; e++) acc[q][nt][e] = 0.f;

    const int nT = K / 64;

#pragma unroll
    for (int s = 0; s < 2; s++) {
        stage_tile_h<128, 512>(sb + s * STG, Ag + s * 64, K, tid);
        stage_tile_h<256, 512>(sb + s * STG + 16384, Bg + s * 64, K, tid);
        asm volatile("cp.async.commit_group;");
    }

    for (int t = 0; t < nT; t++) {
        if (t < nT - 1) asm volatile("cp.async.wait_group 1;" ::: "memory");
        else            asm volatile("cp.async.wait_group 0;" ::: "memory");
        __syncthreads();
        if (t + 2 < nT) {
            const int slot = (t + 2) % 3;
            stage_tile_h<128, 512>(sb + slot * STG, Ag + (t + 2) * 64, K, tid);
            stage_tile_h<256, 512>(sb + slot * STG + 16384, Bg + (t + 2) * 64, K, tid);
            asm volatile("cp.async.commit_group;");
        }
        const uint32_t aBase = sb + (t % 3) * STG;
        const uint32_t bBase = aBase + 16384;
#pragma unroll
        for (int kk2 = 0; kk2 < 8; kk2 += 2) {     // one k16 mma step per iteration
            uint32_t a[2][4];
#pragma unroll
            for (int q = 0; q < 2; q++) {
                const int row = wy * 32 + q * 16 + lrow;
                LDSM4(a[q][0], a[q][1], a[q][2], a[q][3],
                      aBase + row * 128 + (((kk2 + lgh) ^ (row & 7)) << 4));
            }
            uint32_t bfr[NT2][2];
#pragma unroll
            for (int p = 0; p < NPAIR; p++) {
                const int row = wx * 64 + p * 16 + lrow;
                uint32_t r0, r1, r2, r3;
                LDSM4(r0, r1, r2, r3, bBase + row * 128 + (((kk2 + lgh) ^ (row & 7)) << 4));
                bfr[2 * p][0] = r0; bfr[2 * p + 1][0] = r1;
                bfr[2 * p][1] = r2; bfr[2 * p + 1][1] = r3;
            }
#pragma unroll
            for (int q = 0; q < 2; q++)
#pragma unroll
                for (int nt = 0; nt < NT2; nt++)
                    mma_f16(acc[q][nt], a[q][0], a[q][1], a[q][2], a[q][3],
                            bfr[nt][0], bfr[nt][1]);
        }
    }

#pragma unroll
    for (int q = 0; q < 2; q++) {
#pragma unroll
        for (int nt = 0; nt < NT2; nt++) {
#pragma unroll
            for (int eh = 0; eh < 2; eh++) {
                const int m = crow + wy * 32 + q * 16 + gid + eh * 8;
                const int n = ccol + wx * 64 + nt * 8 + tig * 2;
                float2 v;
                v.x = acc[q][nt][eh * 2 + 0] + bias[n];
                v.y = acc[q][nt][eh * 2 + 1] + bias[n + 1];
                if (EPI == 1) {
                    const float2 old = *reinterpret_cast<const float2*>(C + (size_t)m * N + n);
                    v.x = old.x / (1.f + __expf(-v.x));
                    v.y = old.y / (1.f + __expf(-v.y));
                    const int s = m & 127, ch = (m >> 7) & 31, h = n >> 6, b = m >> 12;
                    const int d = n & 63;
                    const size_t idx = ((((size_t)(b * 16 + h) * 32 + ch) * 128 + s) * 64) + d;
                    *reinterpret_cast<float2*>(C2 + idx) = v;
                } else {
                    *reinterpret_cast<float2*>(C + (size_t)m * N + n) = v;
                }
            }
        }
    }
}

// ============ fused MLP (fp16): comb -> gelu(comb@W1+b1) in smem -> @W2+b2 -> scatter ============
// grid 2048 (row blocks of 128), 256 threads (8 warps). 112KB smem.
__global__ __launch_bounds__(256)
void mlp_fused(const __half* __restrict__ comb,
               const __half* __restrict__ w1T, const __half* __restrict__ w2T,
               const float* __restrict__ b1, const float* __restrict__ b2,
               __half* __restrict__ obuf)
{
    extern __shared__ char smem[];
    const uint32_t sb  = smem_u32(smem);
    const uint32_t sW1 = sb;                 // 2 chunks x 16KB = 32KB
    const uint32_t sW2 = sb + 32768;         // 2 chunks x  8KB = 16KB
    const uint32_t sH  = sb + 49152;         // 2 chunks x 16KB = 32KB
    const uint32_t sA  = sb + 81920;         // 2 chunks x 16KB = 32KB

    const int tid = threadIdx.x, wid = tid >> 5, lane = tid & 31;
    const int wy = wid >> 2, wx = wid & 3;               // 2 x 4
    const int gid = lane >> 2, tig = lane & 3;
    const int lrow = lane & 15, lgh = lane >> 4;
    const int crow = blockIdx.x * 128;

    // stage W1 (2 k-chunks of 64), W2, and both A chunks; single group
#pragma unroll
    for (int i = 0; i < 8; i++) {
        const int c = i * 256 + tid;
        const int kt = c >> 10, rem = c & 1023, n = rem >> 3, g4 = rem & 7;
        cp16(sW1 + kt * 16384 + n * 128 + ((g4 ^ (n & 7)) << 4),
             w1T + (size_t)n * 128 + kt * 64 + g4 * 8);
    }
#pragma unroll
    for (int i = 0; i < 4; i++) {
        const int c = i * 256 + tid;
        const int kt = c >> 9, rem = c & 511, n = rem >> 3, g4 = rem & 7;
        cp16(sW2 + kt * 8192 + n * 128 + ((g4 ^ (n & 7)) << 4),
             w2T + (size_t)n * 128 + kt * 64 + g4 * 8);
    }
    stage_tile_h<128, 256>(sA,         comb + (size_t)crow * 128,      128, tid);
    stage_tile_h<128, 256>(sA + 16384, comb + (size_t)crow * 128 + 64, 128, tid);
    asm volatile("cp.async.commit_group;");
    asm volatile("cp.async.wait_group 0;" ::: "memory");
    __syncthreads();

    // GEMM1: 128x128x128, warp tile 64x32
    float acc1[4][4][4];
#pragma unroll
    for (int q = 0; q < 4; q++)
#pragma unroll
        for (int nt = 0; nt < 4; nt++)
#pragma unroll
            for (int e = 0; e < 4; e++) acc1[q][nt][e] = 0.f;

#pragma unroll
    for (int kt = 0; kt < 2; kt++) {
        const uint32_t aBase = sA + kt * 16384;
        const uint32_t bBase = sW1 + kt * 16384;
#pragma unroll
        for (int kk2 = 0; kk2 < 8; kk2 += 2) {
            uint32_t a[4][4];
#pragma unroll
            for (int q = 0; q < 4; q++) {
                const int row = wy * 64 + q * 16 + lrow;
                LDSM4(a[q][0], a[q][1], a[q][2], a[q][3],
                      aBase + row * 128 + (((kk2 + lgh) ^ (row & 7)) << 4));
            }
            uint32_t bfr[4][2];
#pragma unroll
            for (int p = 0; p < 2; p++) {
                const int row = wx * 32 + p * 16 + lrow;
                uint32_t r0, r1, r2, r3;
                LDSM4(r0, r1, r2, r3, bBase + row * 128 + (((kk2 + lgh) ^ (row & 7)) << 4));
                bfr[2 * p][0] = r0; bfr[2 * p + 1][0] = r1;
                bfr[2 * p][1] = r2; bfr[2 * p + 1][1] = r3;
            }
#pragma unroll
            for (int q = 0; q < 4; q++)
#pragma unroll
                for (int nt = 0; nt < 4; nt++)
                    mma_f16(acc1[q][nt], a[q][0], a[q][1], a[q][2], a[q][3],
                            bfr[nt][0], bfr[nt][1]);
        }
    }

    // gelu -> sH (half, A-operand layout: 2 k-chunks of 64)
#pragma unroll
    for (int q = 0; q < 4; q++) {
#pragma unroll
        for (int nt = 0; nt < 4; nt++) {
#pragma unroll
            for (int eh = 0; eh < 2; eh++) {
                const int m = wy * 64 + q * 16 + gid + eh * 8;
                const int n = wx * 32 + nt * 8 + tig * 2;
                float vx = acc1[q][nt][eh * 2 + 0] + b1[n];
                float vy = acc1[q][nt][eh * 2 + 1] + b1[n + 1];
                vx = 0.5f * vx * (1.f + erff(vx * 0.70710678118654752440f));
                vy = 0.5f * vy * (1.f + erff(vy * 0.70710678118654752440f));
                const int kt = n >> 6, g4 = (n & 63) >> 3;
                const uint32_t ad = sH + kt * 16384 + m * 128 +
                                    ((g4 ^ (m & 7)) << 4) + (n & 7) * 2;
                const uint32_t hv = h2u(vx, vy);
                asm volatile("st.shared.u32 [%0], %1;" :: "r"(ad), "r"(hv));
            }
        }
    }
    __syncthreads();

    // GEMM2: 128x64x128, warp tile 64x16
    float acc2[4][2][4];
#pragma unroll
    for (int q = 0; q < 4; q++)
#pragma unroll
        for (int nt = 0; nt < 2; nt++)
#pragma unroll
            for (int e = 0; e < 4; e++) acc2[q][nt][e] = 0.f;

#pragma unroll
    for (int kt = 0; kt < 2; kt++) {
        const uint32_t aBase = sH + kt * 16384;
        const uint32_t bBase = sW2 + kt * 8192;
#pragma unroll
        for (int kk2 = 0; kk2 < 8; kk2 += 2) {
            uint32_t a[4][4];
#pragma unroll
            for (int q = 0; q < 4; q++) {
                const int row = wy * 64 + q * 16 + lrow;
                LDSM4(a[q][0], a[q][1], a[q][2], a[q][3],
                      aBase + row * 128 + (((kk2 + lgh) ^ (row & 7)) << 4));
            }
            uint32_t bfr[2][2];
            {
                const int row = wx * 16 + lrow;
                uint32_t r0, r1, r2, r3;
                LDSM4(r0, r1, r2, r3, bBase + row * 128 + (((kk2 + lgh) ^ (row & 7)) << 4));
                bfr[0][0] = r0; bfr[1][0] = r1; bfr[0][1] = r2; bfr[1][1] = r3;
            }
#pragma unroll
            for (int q = 0; q < 4; q++)
#pragma unroll
                for (int nt = 0; nt < 2; nt++)
                    mma_f16(acc2[q][nt], a[q][0], a[q][1], a[q][2], a[q][3],
                            bfr[nt][0], bfr[nt][1]);
        }
    }

    // epilogue: bias, convert to half, scatter to (b,t,c)
#pragma unroll
    for (int q = 0; q < 4; q++) {
#pragma unroll
        for (int nt = 0; nt < 2; nt++) {
#pragma unroll
            for (int eh = 0; eh < 2; eh++) {
                const int mm = crow + wy * 64 + q * 16 + gid + eh * 8;
                const int n = wx * 16 + nt * 8 + tig * 2;
                const float vx = acc2[q][nt][eh * 2 + 0] + b2[n];
                const float vy = acc2[q][nt][eh * 2 + 1] + b2[n + 1];
                const int s = mm & 127, ch = (mm >> 7) & 31, h = (mm >> 12) & 15, b = mm >> 16;
                const size_t oidx = (((size_t)b * T_) + ch * CS_ + s) * C_ + h * D_ + n;
                *reinterpret_cast<uint32_t*>(obuf + oidx) = h2u(vx, vy);
            }
        }
    }
}

// ============================ converts ============================
__global__ __launch_bounds__(256)
void cvt_half_kernel(const float4* __restrict__ src, uint2* __restrict__ dst, int n4)
{
    const int i = blockIdx.x * blockDim.x + threadIdx.x;
    if (i >= n4) return;
    const float4 v = src[i];
    dst[i] = make_uint2(h2u(v.x, v.y), h2u(v.z, v.w));
}

// W [Kd,Nd] -> Wt half [Nd,Kd]
__global__ void cvt_wt_kernel(const float* __restrict__ W, __half* __restrict__ Wt,
                              int Kd, int Nd)
{
    __shared__ float tile[32][33];
    const int k0 = blockIdx.y * 32, n0 = blockIdx.x * 32;
    const int tx = threadIdx.x, ty = threadIdx.y;
#pragma unroll
    for (int j = 0; j < 32; j += 8)
        tile[ty + j][tx] = W[(size_t)(k0 + ty + j) * Nd + n0 + tx];
    __syncthreads();
#pragma unroll
    for (int j = 0; j < 32; j += 8)
        Wt[(size_t)(n0 + ty + j) * Kd + k0 + tx] = __float2half_rn(tile[tx][ty + j]);
}

// ---------------- in-place per-chunk cumsum + chunk sums ----------------
__global__ void chunk_scan_kernel(float* __restrict__ buf, float* __restrict__ csum)
{
    const int blk = blockIdx.x;        // 2048
    const int d   = threadIdx.x;       // 64
    float* p = buf + (size_t)blk * CS_ * D_ + d;
    float acc = 0.f;
    for (int s = 0; s < CS_; s++) {
        acc += p[(size_t)s * D_];
        p[(size_t)s * D_] = acc;
    }
    csum[(size_t)blk * D_ + d] = acc;
}

// ---------------- cross-chunk exclusive scan + carry LayerNorm ----------------
__global__ void carry_ln_kernel(const float* __restrict__ csum,
                                const float* __restrict__ g,
                                const float* __restrict__ bb,
                                float* __restrict__ ncar)
{
    const int bh = blockIdx.x;
    const int d  = threadIdx.x;
    const int lane = d & 31, w = d >> 5;
    __shared__ float sh[2];
    const float gd = g[d], bd = bb[d];
    float run = 0.f;
    for (int ch = 0; ch < NC_; ch++) {
        const float carry = run;
        run += csum[(size_t)(bh * NC_ + ch) * D_ + d];
        float s = warpSum(carry);
        if (lane == 0) sh[w] = s;
        __syncthreads();
        const float mean = (sh[0] + sh[1]) * (1.f / 64.f);
        __syncthreads();
        const float df = carry - mean;
        float s2 = warpSum(df * df);
        if (lane == 0) sh[w] = s2;
        __syncthreads();
        const float var = (sh[0] + sh[1]) * (1.f / 64.f);
        __syncthreads();
        ncar[(size_t)(bh * NC_ + ch) * D_ + d] = df * rsqrtf(var + EPS_) * gd + bd;
    }
}

// ---------------- cards (LN over D) + comb = [x_h | cards] -> half ----------------
__global__ __launch_bounds__(128)
void cards_comb_kernel(const float* __restrict__ x,
                       const float* __restrict__ lcm,
                       const float* __restrict__ ncar,
                       const float* __restrict__ cg,
                       const float* __restrict__ cb,
                       __half* __restrict__ comb)
{
    const int blk = blockIdx.x;
    const int s   = threadIdx.x;
    const int ch  = blk % NC_;
    const int h   = (blk / NC_) % H_;
    const int b   = blk / (NC_ * H_);

    __shared__ float ncs[D_], gs[D_], bs[D_];
    if (s < D_) { ncs[s] = ncar[(size_t)blk * D_ + s]; gs[s] = cg[s]; bs[s] = cb[s]; }
    __syncthreads();

    float v[D_];
    if (s == 0) {
#pragma unroll
        for (int d = 0; d < D_; d++) v[d] = ncs[d];
    } else {
        const float4* l4 = reinterpret_cast<const float4*>(
            lcm + ((size_t)blk * CS_ + (s - 1)) * D_);
#pragma unroll
        for (int i = 0; i < D_ / 4; i++) {
            const float4 t = l4[i];
            v[4 * i + 0] = t.x + ncs[4 * i + 0];
            v[4 * i + 1] = t.y + ncs[4 * i + 1];
            v[4 * i + 2] = t.z + ncs[4 * i + 2];
            v[4 * i + 3] = t.w + ncs[4 * i + 3];
        }
    }
    float sum = 0.f;
#pragma unroll
    for (int d = 0; d < D_; d++) sum += v[d];
    const float mean = sum * (1.f / 64.f);
    float sq = 0.f;
#pragma unroll
    for (int d = 0; d < D_; d++) { const float df = v[d] - mean; sq += df * df; }
    const float rs = rsqrtf(sq * (1.f / 64.f) + EPS_);

    const size_t row = (size_t)blk * CS_ + s;
    uint32_t* cout = reinterpret_cast<uint32_t*>(comb + row * 128);
    const float4* xr = reinterpret_cast<const float4*>(
        x + (((size_t)b * T_) + ch * CS_ + s) * C_ + h * D_);
#pragma unroll
    for (int i = 0; i < D_ / 4; i++) {
        const float4 t = xr[i];
        cout[2 * i + 0] = h2u(t.x, t.y);
        cout[2 * i + 1] = h2u(t.z, t.w);
    }
#pragma unroll
    for (int i = 0; i < D_ / 2; i++) {
        const float a = (v[2 * i + 0] - mean) * rs * gs[2 * i + 0] + bs[2 * i + 0];
        const float c = (v[2 * i + 1] - mean) * rs * gs[2 * i + 1] + bs[2 * i + 1];
        cout[32 + i] = h2u(a, c);
    }
}

// ---------------- final LayerNorm over C + residual ----------------
__global__ __launch_bounds__(256)
void ln_res_kernel(const float* __restrict__ p, const float* __restrict__ x,
                   const float* __restrict__ g, const float* __restrict__ bb,
                   float* __restrict__ out)
{
    const int row = blockIdx.x;
    const int t   = threadIdx.x;
    const float4 lv = reinterpret_cast<const float4*>(p + (size_t)row * C_)[t];
    float s = lv.x + lv.y + lv.z + lv.w;
    __shared__ float red[8];
    s = warpSum(s);
    if ((t & 31) == 0) red[t >> 5] = s;
    __syncthreads();
    float tot = 0.f;
#pragma unroll
    for (int i = 0; i < 8; i++) tot += red[i];
    const float mean = tot * (1.f / 1024.f);
    __syncthreads();
    const float d0 = lv.x - mean, d1 = lv.y - mean, d2 = lv.z - mean, d3 = lv.w - mean;
    float sq = d0 * d0 + d1 * d1 + d2 * d2 + d3 * d3;
    sq = warpSum(sq);
    if ((t & 31) == 0) red[t >> 5] = sq;
    __syncthreads();
    float v2 = 0.f;
#pragma unroll
    for (int i = 0; i < 8; i++) v2 += red[i];
    const float rs = rsqrtf(v2 * (1.f / 1024.f) + EPS_);
    const float4 xv = reinterpret_cast<const float4*>(x + (size_t)row * C_)[t];
    const float4 gv = reinterpret_cast<const float4*>(g)[t];
    const float4 bv = reinterpret_cast<const float4*>(bb)[t];
    float4 o;
    o.x = xv.x + d0 * rs * gv.x + bv.x;
    o.y = xv.y + d1 * rs * gv.y + bv.y;
    o.z = xv.z + d2 * rs * gv.z + bv.z;
    o.w = xv.w + d3 * rs * gv.w + bv.w;
    reinterpret_cast<float4*>(out + (size_t)row * C_)[t] = o;
}

// ---------------- launch ----------------
extern "C" void kernel_launch(void* const* d_in, const int* in_sizes, int n_in,
                              void* d_out, int out_size)
{
    const float* x       = (const float*)d_in[0];
    const float* mark_W  = (const float*)d_in[1];
    const float* mark_b  = (const float*)d_in[2];
    const float* gate_W  = (const float*)d_in[3];
    const float* gate_b  = (const float*)d_in[4];
    const float* carry_g = (const float*)d_in[5];
    const float* carry_b = (const float*)d_in[6];
    const float* card_g  = (const float*)d_in[7];
    const float* card_b  = (const float*)d_in[8];
    const float* ho1_W   = (const float*)d_in[9];
    const float* ho1_b   = (const float*)d_in[10];
    const float* ho2_W   = (const float*)d_in[11];
    const float* ho2_b   = (const float*)d_in[12];
    const float* proj_W  = (const float*)d_in[13];
    const float* proj_b  = (const float*)d_in[14];
    const float* ln_g    = (const float*)d_in[15];
    const float* ln_b    = (const float*)d_in[16];
    float* out = (float*)d_out;

    static float *pm = nullptr, *scan, *csum, *ncar, *pbuf;
    static __half *xh, *comb, *obuf, *wmT, *wgT, *wpT, *w1T, *w2T;
    if (!pm) {
        cudaGetSymbolAddress((void**)&pm,   g_pm);
        cudaGetSymbolAddress((void**)&scan, g_scan);
        cudaGetSymbolAddress((void**)&csum, g_csum);
        cudaGetSymbolAddress((void**)&ncar, g_ncar);
        cudaGetSymbolAddress((void**)&pbuf, g_pbuf);
        cudaGetSymbolAddress((void**)&xh,   g_xh);
        cudaGetSymbolAddress((void**)&comb, g_comb);
        cudaGetSymbolAddress((void**)&obuf, g_obuf);
        cudaGetSymbolAddress((void**)&wmT,  g_wmT);
        cudaGetSymbolAddress((void**)&wgT,  g_wgT);
        cudaGetSymbolAddress((void**)&wpT,  g_wpT);
        cudaGetSymbolAddress((void**)&w1T,  g_w1T);
        cudaGetSymbolAddress((void**)&w2T,  g_w2T);
        cudaFuncSetAttribute(hgemm<0>, cudaFuncAttributeMaxDynamicSharedMemorySize, 147456);
        cudaFuncSetAttribute(hgemm<1>, cudaFuncAttributeMaxDynamicSharedMemorySize, 147456);
        cudaFuncSetAttribute(mlp_fused, cudaFuncAttributeMaxDynamicSharedMemorySize, 114688);
    }

    const int M  = B_ * T_;              // 16384
    const int n4 = M * C_ / 4;

    // converts
    cvt_half_kernel<<<(n4 + 255) / 256, 256>>>((const float4*)x, (uint2*)xh, n4);
    cvt_wt_kernel<<<dim3(32, 32), dim3(32, 8)>>>(mark_W, wmT, 1024, 1024);
    cvt_wt_kernel<<<dim3(32, 32), dim3(32, 8)>>>(gate_W, wgT, 1024, 1024);
    cvt_wt_kernel<<<dim3(32, 32), dim3(32, 8)>>>(proj_W, wpT, 1024, 1024);
    cvt_wt_kernel<<<dim3(4, 4),   dim3(32, 8)>>>(ho1_W,  w1T, 128, 128);
    cvt_wt_kernel<<<dim3(2, 4),   dim3(32, 8)>>>(ho2_W,  w2T, 128, 64);

    // pm = x @ mark_W + mark_b
    hgemm<0><<<dim3(4, 128), 512, 147456>>>(M, C_, C_, xh, wmT, mark_b, pm, nullptr);
    // gmc (chunked, fp32) = sigmoid(x @ gate_W + gate_b) * pm
    hgemm<1><<<dim3(4, 128), 512, 147456>>>(M, C_, C_, xh, wgT, gate_b, pm, scan);

    chunk_scan_kernel<<<2048, 64>>>(scan, csum);
    carry_ln_kernel<<<B_ * H_, 64>>>(csum, carry_g, carry_b, ncar);
    cards_comb_kernel<<<B_ * H_ * NC_, 128>>>(x, scan, ncar, card_g, card_b, comb);

    // fused MLP: comb -> obuf (half)
    mlp_fused<<<2048, 256, 114688>>>(comb, w1T, w2T, ho1_b, ho2_b, obuf);

    // proj
    hgemm<0><<<dim3(4, 128), 512, 147456>>>(M, C_, C_, obuf, wpT, proj_b, pbuf, nullptr);

    ln_res_kernel<<<M, 256>>>(pbuf, x, ln_g, ln_b, out);
}

// round 12
// speedup vs baseline: 1.5715x; 1.0194x over previous
#include <cuda_runtime.h>
#include <cuda_fp16.h>
#include <math.h>
#include <stdint.h>

#define B_   4
#define T_   4096
#define C_   1024
#define H_   16
#define CS_  128
#define D_   64
#define NC_  32
#define EPS_ 1e-5f

// ---------------- scratch (device globals; no allocations allowed) ----------------
__device__ float  g_pm  [(size_t)16384 * 1024];   // pm [m,n] fp32
__device__ float  g_gmc [(size_t)262144 * 64];    // gm chunked [blk,s,d] fp32
__device__ float  g_csum[2048 * 64];              // chunk sums
__device__ float  g_car [2048 * 64];              // exclusive carries
__device__ float  g_ncar[2048 * 64];              // normalized carries
__device__ float  g_pbuf[(size_t)16384 * 1024];   // proj out pre-LN fp32
__device__ __half g_xh  [(size_t)16384 * 1024];   // x fp16
__device__ __half g_comb[(size_t)262144 * 128];   // [x_h | cards] fp16
__device__ __half g_obuf[(size_t)16384 * 1024];   // mlp out scattered fp16
__device__ __half g_wmT [(size_t)1024 * 1024];    // W^T [N,K] fp16
__device__ __half g_wgT [(size_t)1024 * 1024];
__device__ __half g_wpT [(size_t)1024 * 1024];
__device__ __half g_w1T [128 * 128];
__device__ __half g_w2T [64 * 128];

__device__ __forceinline__ float warpSum(float v) {
#pragma unroll
    for (int o = 16; o > 0; o >>= 1) v += __shfl_xor_sync(0xffffffffu, v, o);
    return v;
}
__device__ __forceinline__ uint32_t smem_u32(const void* p) {
    uint32_t a;
    asm("{ .reg .u64 t; cvta.to.shared.u64 t, %1; cvt.u32.u64 %0, t; }" : "=r"(a) : "l"(p));
    return a;
}
__device__ __forceinline__ void cp16(uint32_t dst, const void* src) {
    asm volatile("cp.async.cg.shared.global [%0], [%1], 16;" :: "r"(dst), "l"(src));
}
#define LDSM4(r0, r1, r2, r3, addr) \
    asm volatile("ldmatrix.sync.aligned.m8n8.x4.shared.b16 {%0,%1,%2,%3}, [%4];" \
        : "=r"(r0), "=r"(r1), "=r"(r2), "=r"(r3) : "r"(addr))
__device__ __forceinline__ void mma_f16(float c[4],
                                        uint32_t a0, uint32_t a1, uint32_t a2, uint32_t a3,
                                        uint32_t b0, uint32_t b1) {
    asm volatile(
        "mma.sync.aligned.m16n8k16.row.col.f32.f16.f16.f32 "
        "{%0,%1,%2,%3}, {%4,%5,%6,%7}, {%8,%9}, {%0,%1,%2,%3};"
        : "+f"(c[0]), "+f"(c[1]), "+f"(c[2]), "+f"(c[3])
        : "r"(a0), "r"(a1), "r"(a2), "r"(a3), "r"(b0), "r"(b1));
}
__device__ __forceinline__ uint32_t h2u(float a, float b) {
    __half2 h = __floats2half2_rn(a, b);
    return *reinterpret_cast<uint32_t*>(&h);
}

// stage ROWS x 64-half tile (128B rows, XOR-granule swizzle) via cp.async; K in halfs
template <int ROWS, int NTH>
__device__ __forceinline__ void stage_tile_h(uint32_t sdst, const __half* __restrict__ gsrc,
                                             int K, int tid) {
#pragma unroll
    for (int i = 0; i < ROWS * 8 / NTH; i++) {
        const int c = i * NTH + tid;
        const int m = c >> 3, g4 = c & 7;
        cp16(sdst + (uint32_t)(m * 128 + ((g4 ^ (m & 7)) << 4)),
             gsrc + (size_t)m * K + g4 * 8);
    }
}

// ============ FP16 GEMM: 128x256x64 CTA k-tile, 512 thr, 3-stage pipeline ============
// A[M,K] half row-major, Bt[N,K] half row-major. Warp grid 4(M)x4(N), warp 32x64.
// EPI 0: C(fp32) = acc+bias.
// EPI 1: C2(fp32 chunked [blk,s,d]) = sigmoid(acc+bias)*C(pm); also writes per-chunk
//        column sums to csum[(b*16+h)*32+ch, d].
template <int EPI>
__global__ __launch_bounds__(512, 1)
void hgemm(int M, int N, int K,
           const __half* __restrict__ A,
           const __half* __restrict__ Bt,
           const float* __restrict__ bias,
           float* __restrict__ C,
           float* __restrict__ C2,
           float* __restrict__ csum)
{
    constexpr int NT2 = 8, NPAIR = 4;          // warp N = 64
    constexpr int STG = 48 * 1024;             // A 16KB + B 32KB per stage

    extern __shared__ char smem[];
    const uint32_t sb = smem_u32(smem);

    const int tid = threadIdx.x, wid = tid >> 5, lane = tid & 31;
    const int wy = wid >> 2, wx = wid & 3;
    const int gid = lane >> 2, tig = lane & 3;
    const int lrow = lane & 15, lgh = lane >> 4;

    const int crow = blockIdx.y * 128, ccol = blockIdx.x * 256;
    const __half* Ag = A + (size_t)crow * K;
    const __half* Bg = Bt + (size_t)ccol * K;

    float acc[2][NT2][4];
#pragma unroll
    for (int q = 0; q < 2; q++)
#pragma unroll
        for (int nt = 0; nt < NT2; nt++)
#pragma unroll
            for (int e = 0; e < 4; e++) acc[q][nt][e] = 0.f;

    const int nT = K / 64;

#pragma unroll
    for (int s = 0; s < 2; s++) {
        stage_tile_h<128, 512>(sb + s * STG, Ag + s * 64, K, tid);
        stage_tile_h<256, 512>(sb + s * STG + 16384, Bg + s * 64, K, tid);
        asm volatile("cp.async.commit_group;");
    }

    for (int t = 0; t < nT; t++) {
        if (t < nT - 1) asm volatile("cp.async.wait_group 1;" ::: "memory");
        else            asm volatile("cp.async.wait_group 0;" ::: "memory");
        __syncthreads();
        if (t + 2 < nT) {
            const int slot = (t + 2) % 3;
            stage_tile_h<128, 512>(sb + slot * STG, Ag + (t + 2) * 64, K, tid);
            stage_tile_h<256, 512>(sb + slot * STG + 16384, Bg + (t + 2) * 64, K, tid);
            asm volatile("cp.async.commit_group;");
        }
        const uint32_t aBase = sb + (t % 3) * STG;
        const uint32_t bBase = aBase + 16384;
#pragma unroll
        for (int kk2 = 0; kk2 < 8; kk2 += 2) {     // one k16 mma step per iteration
            uint32_t a[2][4];
#pragma unroll
            for (int q = 0; q < 2; q++) {
                const int row = wy * 32 + q * 16 + lrow;
                LDSM4(a[q][0], a[q][1], a[q][2], a[q][3],
                      aBase + row * 128 + (((kk2 + lgh) ^ (row & 7)) << 4));
            }
            uint32_t bfr[NT2][2];
#pragma unroll
            for (int p = 0; p < NPAIR; p++) {
                const int row = wx * 64 + p * 16 + lrow;
                uint32_t r0, r1, r2, r3;
                LDSM4(r0, r1, r2, r3, bBase + row * 128 + (((kk2 + lgh) ^ (row & 7)) << 4));
                bfr[2 * p][0] = r0; bfr[2 * p + 1][0] = r1;
                bfr[2 * p][1] = r2; bfr[2 * p + 1][1] = r3;
            }
#pragma unroll
            for (int q = 0; q < 2; q++)
#pragma unroll
                for (int nt = 0; nt < NT2; nt++)
                    mma_f16(acc[q][nt], a[q][0], a[q][1], a[q][2], a[q][3],
                            bfr[nt][0], bfr[nt][1]);
        }
    }

    float colsum[NT2][2];
    if (EPI == 1) {
#pragma unroll
        for (int nt = 0; nt < NT2; nt++) { colsum[nt][0] = 0.f; colsum[nt][1] = 0.f; }
    }

#pragma unroll
    for (int q = 0; q < 2; q++) {
#pragma unroll
        for (int nt = 0; nt < NT2; nt++) {
#pragma unroll
            for (int eh = 0; eh < 2; eh++) {
                const int m = crow + wy * 32 + q * 16 + gid + eh * 8;
                const int n = ccol + wx * 64 + nt * 8 + tig * 2;
                float2 v;
                v.x = acc[q][nt][eh * 2 + 0] + bias[n];
                v.y = acc[q][nt][eh * 2 + 1] + bias[n + 1];
                if (EPI == 1) {
                    const float2 old = *reinterpret_cast<const float2*>(C + (size_t)m * N + n);
                    v.x = old.x / (1.f + __expf(-v.x));
                    v.y = old.y / (1.f + __expf(-v.y));
                    colsum[nt][0] += v.x;
                    colsum[nt][1] += v.y;
                    const int s = m & 127, ch = (m >> 7) & 31, h = n >> 6, b = m >> 12;
                    const int d = n & 63;
                    const size_t idx = ((((size_t)(b * 16 + h) * 32 + ch) * 128 + s) * 64) + d;
                    *reinterpret_cast<float2*>(C2 + idx) = v;
                } else {
                    *reinterpret_cast<float2*>(C + (size_t)m * N + n) = v;
                }
            }
        }
    }

    if (EPI == 1) {
        // per-chunk column sums: reduce over gid lanes, then across wy warps in smem
        __syncthreads();                       // all warps done reading smem tiles
        float* cs = reinterpret_cast<float*>(smem);
        if (tid < 256) cs[tid] = 0.f;
        __syncthreads();
#pragma unroll
        for (int nt = 0; nt < NT2; nt++) {
            float s0 = colsum[nt][0], s1 = colsum[nt][1];
            s0 += __shfl_xor_sync(0xffffffffu, s0, 4);
            s0 += __shfl_xor_sync(0xffffffffu, s0, 8);
            s0 += __shfl_xor_sync(0xffffffffu, s0, 16);
            s1 += __shfl_xor_sync(0xffffffffu, s1, 4);
            s1 += __shfl_xor_sync(0xffffffffu, s1, 8);
            s1 += __shfl_xor_sync(0xffffffffu, s1, 16);
            if (gid == 0) {
                atomicAdd(&cs[wx * 64 + nt * 8 + tig * 2 + 0], s0);
                atomicAdd(&cs[wx * 64 + nt * 8 + tig * 2 + 1], s1);
            }
        }
        __syncthreads();
        if (tid < 256) {
            const int n = ccol + tid, h = n >> 6, d = n & 63;
            const int b = crow >> 12, ch = (crow >> 7) & 31;
            csum[(size_t)((b * 16 + h) * 32 + ch) * 64 + d] = cs[tid];
        }
    }
}

// ============ fused MLP (fp16): comb -> gelu(comb@W1+b1) in smem -> @W2+b2 -> scatter ============
__global__ __launch_bounds__(256)
void mlp_fused(const __half* __restrict__ comb,
               const __half* __restrict__ w1T, const __half* __restrict__ w2T,
               const float* __restrict__ b1, const float* __restrict__ b2,
               __half* __restrict__ obuf)
{
    extern __shared__ char smem[];
    const uint32_t sb  = smem_u32(smem);
    const uint32_t sW1 = sb;                 // 2 chunks x 16KB = 32KB
    const uint32_t sW2 = sb + 32768;         // 2 chunks x  8KB = 16KB
    const uint32_t sH  = sb + 49152;         // 2 chunks x 16KB = 32KB
    const uint32_t sA  = sb + 81920;         // 2 chunks x 16KB = 32KB

    const int tid = threadIdx.x, wid = tid >> 5, lane = tid & 31;
    const int wy = wid >> 2, wx = wid & 3;               // 2 x 4
    const int gid = lane >> 2, tig = lane & 3;
    const int lrow = lane & 15, lgh = lane >> 4;
    const int crow = blockIdx.x * 128;

#pragma unroll
    for (int i = 0; i < 8; i++) {
        const int c = i * 256 + tid;
        const int kt = c >> 10, rem = c & 1023, n = rem >> 3, g4 = rem & 7;
        cp16(sW1 + kt * 16384 + n * 128 + ((g4 ^ (n & 7)) << 4),
             w1T + (size_t)n * 128 + kt * 64 + g4 * 8);
    }
#pragma unroll
    for (int i = 0; i < 4; i++) {
        const int c = i * 256 + tid;
        const int kt = c >> 9, rem = c & 511, n = rem >> 3, g4 = rem & 7;
        cp16(sW2 + kt * 8192 + n * 128 + ((g4 ^ (n & 7)) << 4),
             w2T + (size_t)n * 128 + kt * 64 + g4 * 8);
    }
    stage_tile_h<128, 256>(sA,         comb + (size_t)crow * 128,      128, tid);
    stage_tile_h<128, 256>(sA + 16384, comb + (size_t)crow * 128 + 64, 128, tid);
    asm volatile("cp.async.commit_group;");
    asm volatile("cp.async.wait_group 0;" ::: "memory");
    __syncthreads();

    float acc1[4][4][4];
#pragma unroll
    for (int q = 0; q < 4; q++)
#pragma unroll
        for (int nt = 0; nt < 4; nt++)
#pragma unroll
            for (int e = 0; e < 4; e++) acc1[q][nt][e] = 0.f;

#pragma unroll
    for (int kt = 0; kt < 2; kt++) {
        const uint32_t aBase = sA + kt * 16384;
        const uint32_t bBase = sW1 + kt * 16384;
#pragma unroll
        for (int kk2 = 0; kk2 < 8; kk2 += 2) {
            uint32_t a[4][4];
#pragma unroll
            for (int q = 0; q < 4; q++) {
                const int row = wy * 64 + q * 16 + lrow;
                LDSM4(a[q][0], a[q][1], a[q][2], a[q][3],
                      aBase + row * 128 + (((kk2 + lgh) ^ (row & 7)) << 4));
            }
            uint32_t bfr[4][2];
#pragma unroll
            for (int p = 0; p < 2; p++) {
                const int row = wx * 32 + p * 16 + lrow;
                uint32_t r0, r1, r2, r3;
                LDSM4(r0, r1, r2, r3, bBase + row * 128 + (((kk2 + lgh) ^ (row & 7)) << 4));
                bfr[2 * p][0] = r0; bfr[2 * p + 1][0] = r1;
                bfr[2 * p][1] = r2; bfr[2 * p + 1][1] = r3;
            }
#pragma unroll
            for (int q = 0; q < 4; q++)
#pragma unroll
                for (int nt = 0; nt < 4; nt++)
                    mma_f16(acc1[q][nt], a[q][0], a[q][1], a[q][2], a[q][3],
                            bfr[nt][0], bfr[nt][1]);
        }
    }

#pragma unroll
    for (int q = 0; q < 4; q++) {
#pragma unroll
        for (int nt = 0; nt < 4; nt++) {
#pragma unroll
            for (int eh = 0; eh < 2; eh++) {
                const int m = wy * 64 + q * 16 + gid + eh * 8;
                const int n = wx * 32 + nt * 8 + tig * 2;
                float vx = acc1[q][nt][eh * 2 + 0] + b1[n];
                float vy = acc1[q][nt][eh * 2 + 1] + b1[n + 1];
                vx = 0.5f * vx * (1.f + erff(vx * 0.70710678118654752440f));
                vy = 0.5f * vy * (1.f + erff(vy * 0.70710678118654752440f));
                const int kt = n >> 6, g4 = (n & 63) >> 3;
                const uint32_t ad = sH + kt * 16384 + m * 128 +
                                    ((g4 ^ (m & 7)) << 4) + (n & 7) * 2;
                const uint32_t hv = h2u(vx, vy);
                asm volatile("st.shared.u32 [%0], %1;" :: "r"(ad), "r"(hv));
            }
        }
    }
    __syncthreads();

    float acc2[4][2][4];
#pragma unroll
    for (int q = 0; q < 4; q++)
#pragma unroll
        for (int nt = 0; nt < 2; nt++)
#pragma unroll
            for (int e = 0; e < 4; e++) acc2[q][nt][e] = 0.f;

#pragma unroll
    for (int kt = 0; kt < 2; kt++) {
        const uint32_t aBase = sH + kt * 16384;
        const uint32_t bBase = sW2 + kt * 8192;
#pragma unroll
        for (int kk2 = 0; kk2 < 8; kk2 += 2) {
            uint32_t a[4][4];
#pragma unroll
            for (int q = 0; q < 4; q++) {
                const int row = wy * 64 + q * 16 + lrow;
                LDSM4(a[q][0], a[q][1], a[q][2], a[q][3],
                      aBase + row * 128 + (((kk2 + lgh) ^ (row & 7)) << 4));
            }
            uint32_t bfr[2][2];
            {
                const int row = wx * 16 + lrow;
                uint32_t r0, r1, r2, r3;
                LDSM4(r0, r1, r2, r3, bBase + row * 128 + (((kk2 + lgh) ^ (row & 7)) << 4));
                bfr[0][0] = r0; bfr[1][0] = r1; bfr[0][1] = r2; bfr[1][1] = r3;
            }
#pragma unroll
            for (int q = 0; q < 4; q++)
#pragma unroll
                for (int nt = 0; nt < 2; nt++)
                    mma_f16(acc2[q][nt], a[q][0], a[q][1], a[q][2], a[q][3],
                            bfr[nt][0], bfr[nt][1]);
        }
    }

#pragma unroll
    for (int q = 0; q < 4; q++) {
#pragma unroll
        for (int nt = 0; nt < 2; nt++) {
#pragma unroll
            for (int eh = 0; eh < 2; eh++) {
                const int mm = crow + wy * 64 + q * 16 + gid + eh * 8;
                const int n = wx * 16 + nt * 8 + tig * 2;
                const float vx = acc2[q][nt][eh * 2 + 0] + b2[n];
                const float vy = acc2[q][nt][eh * 2 + 1] + b2[n + 1];
                const int s = mm & 127, ch = (mm >> 7) & 31, h = (mm >> 12) & 15, b = mm >> 16;
                const size_t oidx = (((size_t)b * T_) + ch * CS_ + s) * C_ + h * D_ + n;
                *reinterpret_cast<uint32_t*>(obuf + oidx) = h2u(vx, vy);
            }
        }
    }
}

// ============================ converts ============================
__global__ __launch_bounds__(256)
void cvt_half_kernel(const float4* __restrict__ src, uint2* __restrict__ dst, int n4)
{
    const int i = blockIdx.x * blockDim.x + threadIdx.x;
    if (i >= n4) return;
    const float4 v = src[i];
    dst[i] = make_uint2(h2u(v.x, v.y), h2u(v.z, v.w));
}

__global__ void cvt_wt_kernel(const float* __restrict__ W, __half* __restrict__ Wt,
                              int Kd, int Nd)
{
    __shared__ float tile[32][33];
    const int k0 = blockIdx.y * 32, n0 = blockIdx.x * 32;
    const int tx = threadIdx.x, ty = threadIdx.y;
#pragma unroll
    for (int j = 0; j < 32; j += 8)
        tile[ty + j][tx] = W[(size_t)(k0 + ty + j) * Nd + n0 + tx];
    __syncthreads();
#pragma unroll
    for (int j = 0; j < 32; j += 8)
        Wt[(size_t)(n0 + ty + j) * Kd + k0 + tx] = __float2half_rn(tile[tx][ty + j]);
}

// ---------------- exclusive cross-chunk prefix of csum ----------------
__global__ void scan_csum_kernel(const float* __restrict__ csum, float* __restrict__ carry)
{
    const int bh = blockIdx.x, d = threadIdx.x;   // 64 x 64
    float run = 0.f;
    for (int ch = 0; ch < NC_; ch++) {
        const size_t i = (size_t)(bh * NC_ + ch) * 64 + d;
        carry[i] = run;
        run += csum[i];
    }
}

// ---------------- parallel LN of carries ----------------
__global__ __launch_bounds__(64)
void ln_carry_kernel(const float* __restrict__ carry,
                     const float* __restrict__ g, const float* __restrict__ bb,
                     float* __restrict__ ncar)
{
    const int r = blockIdx.x, d = threadIdx.x;    // 2048 x 64
    const int lane = d & 31, w = d >> 5;
    __shared__ float sh[2];
    const float val = carry[(size_t)r * 64 + d];
    float s = warpSum(val);
    if (lane == 0) sh[w] = s;
    __syncthreads();
    const float mean = (sh[0] + sh[1]) * (1.f / 64.f);
    __syncthreads();
    const float df = val - mean;
    float s2 = warpSum(df * df);
    if (lane == 0) sh[w] = s2;
    __syncthreads();
    const float var = (sh[0] + sh[1]) * (1.f / 64.f);
    ncar[(size_t)r * 64 + d] = df * rsqrtf(var + EPS_) * g[d] + bb[d];
}

// ---------------- fused: in-smem chunk cumsum + cards LN + comb assembly ----------------
__global__ __launch_bounds__(128)
void scan_cards_kernel(const float* __restrict__ gmc,
                       const float* __restrict__ x,
                       const float* __restrict__ ncar,
                       const float* __restrict__ cg,
                       const float* __restrict__ cb,
                       __half* __restrict__ comb)
{
    __shared__ float gm[128 * 65];                 // 65-pad: conflict-free col scan + row reads
    __shared__ float ncs[D_], gs[D_], bs[D_];
    const int blk = blockIdx.x, tid = threadIdx.x;
    const int ch = blk % NC_, h = (blk / NC_) % H_, b = blk / (NC_ * H_);

    const float4* src = reinterpret_cast<const float4*>(gmc + (size_t)blk * CS_ * D_);
#pragma unroll
    for (int i = 0; i < 16; i++) {
        const int e = tid + i * 128;               // float4 index 0..2047
        const int s = e >> 4, d4 = (e & 15) * 4;
        const float4 t = src[e];
        float* p = &gm[s * 65 + d4];
        p[0] = t.x; p[1] = t.y; p[2] = t.z; p[3] = t.w;
    }
    if (tid < D_) { ncs[tid] = ncar[(size_t)blk * D_ + tid]; gs[tid] = cg[tid]; bs[tid] = cb[tid]; }
    __syncthreads();

    if (tid < D_) {                                // serial inclusive scan per column
        float acc = 0.f;
#pragma unroll 4
        for (int s = 0; s < CS_; s++) { acc += gm[s * 65 + tid]; gm[s * 65 + tid] = acc; }
    }
    __syncthreads();

    const int s = tid;
    float v[D_];
    if (s == 0) {
#pragma unroll
        for (int d = 0; d < D_; d++) v[d] = ncs[d];
    } else {
        const float* row = &gm[(s - 1) * 65];
#pragma unroll
        for (int d = 0; d < D_; d++) v[d] = row[d] + ncs[d];
    }
    float sum = 0.f;
#pragma unroll
    for (int d = 0; d < D_; d++) sum += v[d];
    const float mean = sum * (1.f / 64.f);
    float sq = 0.f;
#pragma unroll
    for (int d = 0; d < D_; d++) { const float df = v[d] - mean; sq += df * df; }
    const float rs = rsqrtf(sq * (1.f / 64.f) + EPS_);

    const size_t row = (size_t)blk * CS_ + s;
    uint32_t* cout = reinterpret_cast<uint32_t*>(comb + row * 128);
    const float4* xr = reinterpret_cast<const float4*>(
        x + (((size_t)b * T_) + ch * CS_ + s) * C_ + h * D_);
#pragma unroll
    for (int i = 0; i < D_ / 4; i++) {
        const float4 t = xr[i];
        cout[2 * i + 0] = h2u(t.x, t.y);
        cout[2 * i + 1] = h2u(t.z, t.w);
    }
#pragma unroll
    for (int i = 0; i < D_ / 2; i++) {
        const float a = (v[2 * i + 0] - mean) * rs * gs[2 * i + 0] + bs[2 * i + 0];
        const float c = (v[2 * i + 1] - mean) * rs * gs[2 * i + 1] + bs[2 * i + 1];
        cout[32 + i] = h2u(a, c);
    }
}

// ---------------- final LayerNorm over C + residual ----------------
__global__ __launch_bounds__(256)
void ln_res_kernel(const float* __restrict__ p, const float* __restrict__ x,
                   const float* __restrict__ g, const float* __restrict__ bb,
                   float* __restrict__ out)
{
    const int row = blockIdx.x;
    const int t   = threadIdx.x;
    const float4 lv = reinterpret_cast<const float4*>(p + (size_t)row * C_)[t];
    float s = lv.x + lv.y + lv.z + lv.w;
    __shared__ float red[8];
    s = warpSum(s);
    if ((t & 31) == 0) red[t >> 5] = s;
    __syncthreads();
    float tot = 0.f;
#pragma unroll
    for (int i = 0; i < 8; i++) tot += red[i];
    const float mean = tot * (1.f / 1024.f);
    __syncthreads();
    const float d0 = lv.x - mean, d1 = lv.y - mean, d2 = lv.z - mean, d3 = lv.w - mean;
    float sq = d0 * d0 + d1 * d1 + d2 * d2 + d3 * d3;
    sq = warpSum(sq);
    if ((t & 31) == 0) red[t >> 5] = sq;
    __syncthreads();
    float v2 = 0.f;
#pragma unroll
    for (int i = 0; i < 8; i++) v2 += red[i];
    const float rs = rsqrtf(v2 * (1.f / 1024.f) + EPS_);
    const float4 xv = reinterpret_cast<const float4*>(x + (size_t)row * C_)[t];
    const float4 gv = reinterpret_cast<const float4*>(g)[t];
    const float4 bv = reinterpret_cast<const float4*>(bb)[t];
    float4 o;
    o.x = xv.x + d0 * rs * gv.x + bv.x;
    o.y = xv.y + d1 * rs * gv.y + bv.y;
    o.z = xv.z + d2 * rs * gv.z + bv.z;
    o.w = xv.w + d3 * rs * gv.w + bv.w;
    reinterpret_cast<float4*>(out + (size_t)row * C_)[t] = o;
}

// ---------------- launch ----------------
extern "C" void kernel_launch(void* const* d_in, const int* in_sizes, int n_in,
                              void* d_out, int out_size)
{
    const float* x       = (const float*)d_in[0];
    const float* mark_W  = (const float*)d_in[1];
    const float* mark_b  = (const float*)d_in[2];
    const float* gate_W  = (const float*)d_in[3];
    const float* gate_b  = (const float*)d_in[4];
    const float* carry_g = (const float*)d_in[5];
    const float* carry_b = (const float*)d_in[6];
    const float* card_g  = (const float*)d_in[7];
    const float* card_b  = (const float*)d_in[8];
    const float* ho1_W   = (const float*)d_in[9];
    const float* ho1_b   = (const float*)d_in[10];
    const float* ho2_W   = (const float*)d_in[11];
    const float* ho2_b   = (const float*)d_in[12];
    const float* proj_W  = (const float*)d_in[13];
    const float* proj_b  = (const float*)d_in[14];
    const float* ln_g    = (const float*)d_in[15];
    const float* ln_b    = (const float*)d_in[16];
    float* out = (float*)d_out;

    static float *pm = nullptr, *gmc, *csum, *car, *ncar, *pbuf;
    static __half *xh, *comb, *obuf, *wmT, *wgT, *wpT, *w1T, *w2T;
    if (!pm) {
        cudaGetSymbolAddress((void**)&pm,   g_pm);
        cudaGetSymbolAddress((void**)&gmc,  g_gmc);
        cudaGetSymbolAddress((void**)&csum, g_csum);
        cudaGetSymbolAddress((void**)&car,  g_car);
        cudaGetSymbolAddress((void**)&ncar, g_ncar);
        cudaGetSymbolAddress((void**)&pbuf, g_pbuf);
        cudaGetSymbolAddress((void**)&xh,   g_xh);
        cudaGetSymbolAddress((void**)&comb, g_comb);
        cudaGetSymbolAddress((void**)&obuf, g_obuf);
        cudaGetSymbolAddress((void**)&wmT,  g_wmT);
        cudaGetSymbolAddress((void**)&wgT,  g_wgT);
        cudaGetSymbolAddress((void**)&wpT,  g_wpT);
        cudaGetSymbolAddress((void**)&w1T,  g_w1T);
        cudaGetSymbolAddress((void**)&w2T,  g_w2T);
        cudaFuncSetAttribute(hgemm<0>, cudaFuncAttributeMaxDynamicSharedMemorySize, 147456);
        cudaFuncSetAttribute(hgemm<1>, cudaFuncAttributeMaxDynamicSharedMemorySize, 147456);
        cudaFuncSetAttribute(mlp_fused, cudaFuncAttributeMaxDynamicSharedMemorySize, 114688);
    }

    const int M  = B_ * T_;              // 16384
    const int n4 = M * C_ / 4;

    // launches 1-5 (ncu -s 5 skips these; launch 6 = hgemm<0> gets profiled)
    cvt_half_kernel<<<(n4 + 255) / 256, 256>>>((const float4*)x, (uint2*)xh, n4);
    cvt_wt_kernel<<<dim3(32, 32), dim3(32, 8)>>>(mark_W, wmT, 1024, 1024);
    cvt_wt_kernel<<<dim3(32, 32), dim3(32, 8)>>>(gate_W, wgT, 1024, 1024);
    cvt_wt_kernel<<<dim3(32, 32), dim3(32, 8)>>>(proj_W, wpT, 1024, 1024);
    cvt_wt_kernel<<<dim3(4, 4),   dim3(32, 8)>>>(ho1_W,  w1T, 128, 128);

    // 6: pm = x @ mark_W + mark_b   (profiled by ncu)
    hgemm<0><<<dim3(4, 128), 512, 147456>>>(M, C_, C_, xh, wmT, mark_b, pm, nullptr, nullptr);
    // 7: gmc = sigmoid(x @ gate_W + gate_b) * pm, + per-chunk csum
    hgemm<1><<<dim3(4, 128), 512, 147456>>>(M, C_, C_, xh, wgT, gate_b, pm, gmc, csum);

    // 8: w2 convert (needed only by mlp_fused)
    cvt_wt_kernel<<<dim3(2, 4), dim3(32, 8)>>>(ho2_W, w2T, 128, 64);

    // 9-11: carry chain + fused scan/cards
    scan_csum_kernel<<<B_ * H_, 64>>>(csum, car);
    ln_carry_kernel<<<2048, 64>>>(car, carry_g, carry_b, ncar);
    scan_cards_kernel<<<2048, 128>>>(gmc, x, ncar, card_g, card_b, comb);

    // 12: fused MLP
    mlp_fused<<<2048, 256, 114688>>>(comb, w1T, w2T, ho1_b, ho2_b, obuf);

    // 13: proj
    hgemm<0><<<dim3(4, 128), 512, 147456>>>(M, C_, C_, obuf, wpT, proj_b, pbuf, nullptr, nullptr);

    // 14: final LN + residual
    ln_res_kernel<<<M, 256>>>(pbuf, x, ln_g, ln_b, out);
}

// round 13
// speedup vs baseline: 1.6636x; 1.0586x over previous
#include <cuda_runtime.h>
#include <cuda_fp16.h>
#include <math.h>
#include <stdint.h>

#define B_   4
#define T_   4096
#define C_   1024
#define H_   16
#define CS_  128
#define D_   64
#define NC_  32
#define EPS_ 1e-5f

// ---------------- scratch (device globals; no allocations allowed) ----------------
__device__ __half g_pmh [(size_t)16384 * 1024];   // pm fp16
__device__ float  g_gmc [(size_t)262144 * 64];    // gm chunked [blk,s,d] fp32
__device__ float  g_csum[2048 * 64];
__device__ float  g_car [2048 * 64];
__device__ float  g_ncar[2048 * 64];
__device__ float  g_pbuf[(size_t)16384 * 1024];   // proj out pre-LN fp32
__device__ __half g_xh  [(size_t)16384 * 1024];   // x fp16
__device__ __half g_obuf[(size_t)16384 * 1024];   // mlp out scattered fp16
__device__ __half g_wmT [(size_t)1024 * 1024];    // W^T [N,K] fp16
__device__ __half g_wgT [(size_t)1024 * 1024];
__device__ __half g_wpT [(size_t)1024 * 1024];
__device__ __half g_w1T [128 * 128];
__device__ __half g_w2T [64 * 128];

__device__ __forceinline__ float warpSum(float v) {
#pragma unroll
    for (int o = 16; o > 0; o >>= 1) v += __shfl_xor_sync(0xffffffffu, v, o);
    return v;
}
__device__ __forceinline__ uint32_t smem_u32(const void* p) {
    uint32_t a;
    asm("{ .reg .u64 t; cvta.to.shared.u64 t, %1; cvt.u32.u64 %0, t; }" : "=r"(a) : "l"(p));
    return a;
}
__device__ __forceinline__ void cp16(uint32_t dst, const void* src) {
    asm volatile("cp.async.cg.shared.global [%0], [%1], 16;" :: "r"(dst), "l"(src));
}
#define LDSM4(r0, r1, r2, r3, addr) \
    asm volatile("ldmatrix.sync.aligned.m8n8.x4.shared.b16 {%0,%1,%2,%3}, [%4];" \
        : "=r"(r0), "=r"(r1), "=r"(r2), "=r"(r3) : "r"(addr))
__device__ __forceinline__ void mma_f16(float c[4],
                                        uint32_t a0, uint32_t a1, uint32_t a2, uint32_t a3,
                                        uint32_t b0, uint32_t b1) {
    asm volatile(
        "mma.sync.aligned.m16n8k16.row.col.f32.f16.f16.f32 "
        "{%0,%1,%2,%3}, {%4,%5,%6,%7}, {%8,%9}, {%0,%1,%2,%3};"
        : "+f"(c[0]), "+f"(c[1]), "+f"(c[2]), "+f"(c[3])
        : "r"(a0), "r"(a1), "r"(a2), "r"(a3), "r"(b0), "r"(b1));
}
__device__ __forceinline__ uint32_t h2u(float a, float b) {
    __half2 h = __floats2half2_rn(a, b);
    return *reinterpret_cast<uint32_t*>(&h);
}

// stage ROWS x 64-half tile (128B rows, XOR-granule swizzle) via cp.async; K in halfs
template <int ROWS, int NTH>
__device__ __forceinline__ void stage_tile_h(uint32_t sdst, const __half* __restrict__ gsrc,
                                             int K, int tid) {
#pragma unroll
    for (int i = 0; i < ROWS * 8 / NTH; i++) {
        const int c = i * NTH + tid;
        const int m = c >> 3, g4 = c & 7;
        cp16(sdst + (uint32_t)(m * 128 + ((g4 ^ (m & 7)) << 4)),
             gsrc + (size_t)m * K + g4 * 8);
    }
}

// ============ FP16 GEMM: 128x256x64 CTA k-tile, 512 thr, 3-stage pipeline ============
// EPI 0: Cf(fp32) = acc+bias.   EPI 2: Ch(fp16) = acc+bias.
// EPI 1: C2(fp32 chunked) = sigmoid(acc+bias)*Ch(pm fp16); + per-chunk csum.
template <int EPI>
__global__ __launch_bounds__(512, 1)
void hgemm(int M, int N, int K,
           const __half* __restrict__ A,
           const __half* __restrict__ Bt,
           const float* __restrict__ bias,
           float* __restrict__ Cf,
           __half* __restrict__ Ch,
           float* __restrict__ C2,
           float* __restrict__ csum)
{
    constexpr int NT2 = 8, NPAIR = 4;
    constexpr int STG = 48 * 1024;

    extern __shared__ char smem[];
    const uint32_t sb = smem_u32(smem);

    const int tid = threadIdx.x, wid = tid >> 5, lane = tid & 31;
    const int wy = wid >> 2, wx = wid & 3;
    const int gid = lane >> 2, tig = lane & 3;
    const int lrow = lane & 15, lgh = lane >> 4;

    const int crow = blockIdx.y * 128, ccol = blockIdx.x * 256;
    const __half* Ag = A + (size_t)crow * K;
    const __half* Bg = Bt + (size_t)ccol * K;

    float acc[2][NT2][4];
#pragma unroll
    for (int q = 0; q < 2; q++)
#pragma unroll
        for (int nt = 0; nt < NT2; nt++)
#pragma unroll
            for (int e = 0; e < 4; e++) acc[q][nt][e] = 0.f;

    const int nT = K / 64;

#pragma unroll
    for (int s = 0; s < 2; s++) {
        stage_tile_h<128, 512>(sb + s * STG, Ag + s * 64, K, tid);
        stage_tile_h<256, 512>(sb + s * STG + 16384, Bg + s * 64, K, tid);
        asm volatile("cp.async.commit_group;");
    }

    for (int t = 0; t < nT; t++) {
        if (t < nT - 1) asm volatile("cp.async.wait_group 1;" ::: "memory");
        else            asm volatile("cp.async.wait_group 0;" ::: "memory");
        __syncthreads();
        if (t + 2 < nT) {
            const int slot = (t + 2) % 3;
            stage_tile_h<128, 512>(sb + slot * STG, Ag + (t + 2) * 64, K, tid);
            stage_tile_h<256, 512>(sb + slot * STG + 16384, Bg + (t + 2) * 64, K, tid);
            asm volatile("cp.async.commit_group;");
        }
        const uint32_t aBase = sb + (t % 3) * STG;
        const uint32_t bBase = aBase + 16384;
#pragma unroll
        for (int kk2 = 0; kk2 < 8; kk2 += 2) {
            uint32_t a[2][4];
#pragma unroll
            for (int q = 0; q < 2; q++) {
                const int row = wy * 32 + q * 16 + lrow;
                LDSM4(a[q][0], a[q][1], a[q][2], a[q][3],
                      aBase + row * 128 + (((kk2 + lgh) ^ (row & 7)) << 4));
            }
            uint32_t bfr[NT2][2];
#pragma unroll
            for (int p = 0; p < NPAIR; p++) {
                const int row = wx * 64 + p * 16 + lrow;
                uint32_t r0, r1, r2, r3;
                LDSM4(r0, r1, r2, r3, bBase + row * 128 + (((kk2 + lgh) ^ (row & 7)) << 4));
                bfr[2 * p][0] = r0; bfr[2 * p + 1][0] = r1;
                bfr[2 * p][1] = r2; bfr[2 * p + 1][1] = r3;
            }
#pragma unroll
            for (int q = 0; q < 2; q++)
#pragma unroll
                for (int nt = 0; nt < NT2; nt++)
                    mma_f16(acc[q][nt], a[q][0], a[q][1], a[q][2], a[q][3],
                            bfr[nt][0], bfr[nt][1]);
        }
    }

    float colsum[NT2][2];
    if (EPI == 1) {
#pragma unroll
        for (int nt = 0; nt < NT2; nt++) { colsum[nt][0] = 0.f; colsum[nt][1] = 0.f; }
    }

#pragma unroll
    for (int q = 0; q < 2; q++) {
#pragma unroll
        for (int nt = 0; nt < NT2; nt++) {
#pragma unroll
            for (int eh = 0; eh < 2; eh++) {
                const int m = crow + wy * 32 + q * 16 + gid + eh * 8;
                const int n = ccol + wx * 64 + nt * 8 + tig * 2;
                float2 v;
                v.x = acc[q][nt][eh * 2 + 0] + bias[n];
                v.y = acc[q][nt][eh * 2 + 1] + bias[n + 1];
                if (EPI == 1) {
                    const uint32_t ou = *reinterpret_cast<const uint32_t*>(Ch + (size_t)m * N + n);
                    const float2 old = __half22float2(*reinterpret_cast<const __half2*>(&ou));
                    v.x = old.x / (1.f + __expf(-v.x));
                    v.y = old.y / (1.f + __expf(-v.y));
                    colsum[nt][0] += v.x;
                    colsum[nt][1] += v.y;
                    const int s = m & 127, ch = (m >> 7) & 31, h = n >> 6, b = m >> 12;
                    const int d = n & 63;
                    const size_t idx = ((((size_t)(b * 16 + h) * 32 + ch) * 128 + s) * 64) + d;
                    *reinterpret_cast<float2*>(C2 + idx) = v;
                } else if (EPI == 2) {
                    *reinterpret_cast<uint32_t*>(Ch + (size_t)m * N + n) = h2u(v.x, v.y);
                } else {
                    *reinterpret_cast<float2*>(Cf + (size_t)m * N + n) = v;
                }
            }
        }
    }

    if (EPI == 1) {
        __syncthreads();
        float* cs = reinterpret_cast<float*>(smem);
        if (tid < 256) cs[tid] = 0.f;
        __syncthreads();
#pragma unroll
        for (int nt = 0; nt < NT2; nt++) {
            float s0 = colsum[nt][0], s1 = colsum[nt][1];
            s0 += __shfl_xor_sync(0xffffffffu, s0, 4);
            s0 += __shfl_xor_sync(0xffffffffu, s0, 8);
            s0 += __shfl_xor_sync(0xffffffffu, s0, 16);
            s1 += __shfl_xor_sync(0xffffffffu, s1, 4);
            s1 += __shfl_xor_sync(0xffffffffu, s1, 8);
            s1 += __shfl_xor_sync(0xffffffffu, s1, 16);
            if (gid == 0) {
                atomicAdd(&cs[wx * 64 + nt * 8 + tig * 2 + 0], s0);
                atomicAdd(&cs[wx * 64 + nt * 8 + tig * 2 + 1], s1);
            }
        }
        __syncthreads();
        if (tid < 256) {
            const int n = ccol + tid, h = n >> 6, d = n & 63;
            const int b = crow >> 12, ch = (crow >> 7) & 31;
            csum[(size_t)((b * 16 + h) * 32 + ch) * 64 + d] = cs[tid];
        }
    }
}

// ============ fused: chunk scan + cards LN + comb(in smem) + MLP -> obuf ============
// grid 2048, 256 threads. smem: W1 32K | W2 16K | A(comb) 32K | GM/H 32.5K = 112.5K
__global__ __launch_bounds__(256)
void scan_mlp(const float* __restrict__ gmc,
              const float* __restrict__ x,
              const float* __restrict__ ncar,
              const float* __restrict__ cg, const float* __restrict__ cb,
              const __half* __restrict__ w1T, const __half* __restrict__ w2T,
              const float* __restrict__ b1, const float* __restrict__ b2,
              __half* __restrict__ obuf)
{
    extern __shared__ char smem[];
    const uint32_t sb  = smem_u32(smem);
    const uint32_t sW1 = sb;                  // 32768
    const uint32_t sW2 = sb + 32768;          // 16384
    const uint32_t sA  = sb + 49152;          // 32768 (comb fp16, 2 kt chunks)
    const uint32_t sGM = sb + 81920;          // 33280 (scan buffer; reused as sH)
    const uint32_t sH  = sGM;
    float* gm = reinterpret_cast<float*>(smem + 81920);

    const int tid = threadIdx.x, wid = tid >> 5, lane = tid & 31;
    const int wy = wid >> 2, wx = wid & 3;
    const int gid = lane >> 2, tig = lane & 3;
    const int lrow = lane & 15, lgh = lane >> 4;
    const int blk = blockIdx.x;
    const int ch = blk % NC_, h = (blk / NC_) % H_, b = blk / (NC_ * H_);

    __shared__ float ncs[D_], gs[D_], bs[D_];

    // stage W1/W2 via cp.async (overlaps scan phase)
#pragma unroll
    for (int i = 0; i < 8; i++) {
        const int c = i * 256 + tid;
        const int kt = c >> 10, rem = c & 1023, n = rem >> 3, g4 = rem & 7;
        cp16(sW1 + kt * 16384 + n * 128 + ((g4 ^ (n & 7)) << 4),
             w1T + (size_t)n * 128 + kt * 64 + g4 * 8);
    }
#pragma unroll
    for (int i = 0; i < 4; i++) {
        const int c = i * 256 + tid;
        const int kt = c >> 9, rem = c & 511, n = rem >> 3, g4 = rem & 7;
        cp16(sW2 + kt * 8192 + n * 128 + ((g4 ^ (n & 7)) << 4),
             w2T + (size_t)n * 128 + kt * 64 + g4 * 8);
    }
    asm volatile("cp.async.commit_group;");

    // load gm chunk [128 s][64 d] into padded smem
    const float4* src = reinterpret_cast<const float4*>(gmc + (size_t)blk * CS_ * D_);
#pragma unroll
    for (int i = 0; i < 8; i++) {
        const int e = tid + i * 256;
        const int s = e >> 4, d4 = (e & 15) * 4;
        const float4 t = src[e];
        float* p = &gm[s * 65 + d4];
        p[0] = t.x; p[1] = t.y; p[2] = t.z; p[3] = t.w;
    }
    if (tid < D_) { ncs[tid] = ncar[(size_t)blk * D_ + tid]; gs[tid] = cg[tid]; bs[tid] = cb[tid]; }
    __syncthreads();

    if (tid < D_) {                            // serial inclusive scan per column
        float acc = 0.f;
#pragma unroll 4
        for (int s = 0; s < CS_; s++) { acc += gm[s * 65 + tid]; gm[s * 65 + tid] = acc; }
    }
    __syncthreads();

    // cards LN + comb build straight into sA (fp16, staged layout)
    if (tid < 128) {
        const int s = tid;
        float v[D_];
        if (s == 0) {
#pragma unroll
            for (int d = 0; d < D_; d++) v[d] = ncs[d];
        } else {
            const float* row = &gm[(s - 1) * 65];
#pragma unroll
            for (int d = 0; d < D_; d++) v[d] = row[d] + ncs[d];
        }
        float sum = 0.f;
#pragma unroll
        for (int d = 0; d < D_; d++) sum += v[d];
        const float mean = sum * (1.f / 64.f);
        float sq = 0.f;
#pragma unroll
        for (int d = 0; d < D_; d++) { const float df = v[d] - mean; sq += df * df; }
        const float rs = rsqrtf(sq * (1.f / 64.f) + EPS_);

        const uint32_t rowbase0 = sA + s * 128;            // kt 0 (x part)
        const uint32_t rowbase1 = sA + 16384 + s * 128;    // kt 1 (cards)
        const float4* xr = reinterpret_cast<const float4*>(
            x + (((size_t)b * T_) + ch * CS_ + s) * C_ + h * D_);
#pragma unroll
        for (int i = 0; i < 16; i++) {                     // x halfs, d = 4i..4i+3
            const float4 t = xr[i];
            const int d = 4 * i, g4 = d >> 3;
            const uint32_t ad = rowbase0 + ((g4 ^ (s & 7)) << 4) + (d & 7) * 2;
            const uint32_t u0 = h2u(t.x, t.y), u1 = h2u(t.z, t.w);
            asm volatile("st.shared.u32 [%0], %1;" :: "r"(ad), "r"(u0));
            asm volatile("st.shared.u32 [%0], %1;" :: "r"(ad + 4), "r"(u1));
        }
#pragma unroll
        for (int i = 0; i < 32; i++) {                     // card halfs, d = 2i, 2i+1
            const float a = (v[2 * i + 0] - mean) * rs * gs[2 * i + 0] + bs[2 * i + 0];
            const float c = (v[2 * i + 1] - mean) * rs * gs[2 * i + 1] + bs[2 * i + 1];
            const int d = 2 * i, g4 = d >> 3;
            const uint32_t ad = rowbase1 + ((g4 ^ (s & 7)) << 4) + (d & 7) * 2;
            const uint32_t u = h2u(a, c);
            asm volatile("st.shared.u32 [%0], %1;" :: "r"(ad), "r"(u));
        }
    }
    asm volatile("cp.async.wait_group 0;" ::: "memory");
    __syncthreads();

    // GEMM1: 128x128x128, warp tile 64x32
    float acc1[4][4][4];
#pragma unroll
    for (int q = 0; q < 4; q++)
#pragma unroll
        for (int nt = 0; nt < 4; nt++)
#pragma unroll
            for (int e = 0; e < 4; e++) acc1[q][nt][e] = 0.f;

#pragma unroll
    for (int kt = 0; kt < 2; kt++) {
        const uint32_t aBase = sA + kt * 16384;
        const uint32_t bBase = sW1 + kt * 16384;
#pragma unroll
        for (int kk2 = 0; kk2 < 8; kk2 += 2) {
            uint32_t a[4][4];
#pragma unroll
            for (int q = 0; q < 4; q++) {
                const int row = wy * 64 + q * 16 + lrow;
                LDSM4(a[q][0], a[q][1], a[q][2], a[q][3],
                      aBase + row * 128 + (((kk2 + lgh) ^ (row & 7)) << 4));
            }
            uint32_t bfr[4][2];
#pragma unroll
            for (int p = 0; p < 2; p++) {
                const int row = wx * 32 + p * 16 + lrow;
                uint32_t r0, r1, r2, r3;
                LDSM4(r0, r1, r2, r3, bBase + row * 128 + (((kk2 + lgh) ^ (row & 7)) << 4));
                bfr[2 * p][0] = r0; bfr[2 * p + 1][0] = r1;
                bfr[2 * p][1] = r2; bfr[2 * p + 1][1] = r3;
            }
#pragma unroll
            for (int q = 0; q < 4; q++)
#pragma unroll
                for (int nt = 0; nt < 4; nt++)
                    mma_f16(acc1[q][nt], a[q][0], a[q][1], a[q][2], a[q][3],
                            bfr[nt][0], bfr[nt][1]);
        }
    }
    __syncthreads();   // gm scan buffer now dead; safe to overwrite as sH

    // gelu -> sH (half, A-operand layout: 2 k-chunks of 64)
#pragma unroll
    for (int q = 0; q < 4; q++) {
#pragma unroll
        for (int nt = 0; nt < 4; nt++) {
#pragma unroll
            for (int eh = 0; eh < 2; eh++) {
                const int m = wy * 64 + q * 16 + gid + eh * 8;
                const int n = wx * 32 + nt * 8 + tig * 2;
                float vx = acc1[q][nt][eh * 2 + 0] + b1[n];
                float vy = acc1[q][nt][eh * 2 + 1] + b1[n + 1];
                vx = 0.5f * vx * (1.f + erff(vx * 0.70710678118654752440f));
                vy = 0.5f * vy * (1.f + erff(vy * 0.70710678118654752440f));
                const int kt = n >> 6, g4 = (n & 63) >> 3;
                const uint32_t ad = sH + kt * 16384 + m * 128 +
                                    ((g4 ^ (m & 7)) << 4) + (n & 7) * 2;
                const uint32_t hv = h2u(vx, vy);
                asm volatile("st.shared.u32 [%0], %1;" :: "r"(ad), "r"(hv));
            }
        }
    }
    __syncthreads();

    // GEMM2: 128x64x128, warp tile 64x16
    float acc2[4][2][4];
#pragma unroll
    for (int q = 0; q < 4; q++)
#pragma unroll
        for (int nt = 0; nt < 2; nt++)
#pragma unroll
            for (int e = 0; e < 4; e++) acc2[q][nt][e] = 0.f;

#pragma unroll
    for (int kt = 0; kt < 2; kt++) {
        const uint32_t aBase = sH + kt * 16384;
        const uint32_t bBase = sW2 + kt * 8192;
#pragma unroll
        for (int kk2 = 0; kk2 < 8; kk2 += 2) {
            uint32_t a[4][4];
#pragma unroll
            for (int q = 0; q < 4; q++) {
                const int row = wy * 64 + q * 16 + lrow;
                LDSM4(a[q][0], a[q][1], a[q][2], a[q][3],
                      aBase + row * 128 + (((kk2 + lgh) ^ (row & 7)) << 4));
            }
            uint32_t bfr[2][2];
            {
                const int row = wx * 16 + lrow;
                uint32_t r0, r1, r2, r3;
                LDSM4(r0, r1, r2, r3, bBase + row * 128 + (((kk2 + lgh) ^ (row & 7)) << 4));
                bfr[0][0] = r0; bfr[1][0] = r1; bfr[0][1] = r2; bfr[1][1] = r3;
            }
#pragma unroll
            for (int q = 0; q < 4; q++)
#pragma unroll
                for (int nt = 0; nt < 2; nt++)
                    mma_f16(acc2[q][nt], a[q][0], a[q][1], a[q][2], a[q][3],
                            bfr[nt][0], bfr[nt][1]);
        }
    }

    // epilogue: bias, half, scatter to (b,t,c)
#pragma unroll
    for (int q = 0; q < 4; q++) {
#pragma unroll
        for (int nt = 0; nt < 2; nt++) {
#pragma unroll
            for (int eh = 0; eh < 2; eh++) {
                const int mm = blk * 128 + wy * 64 + q * 16 + gid + eh * 8;
                const int n = wx * 16 + nt * 8 + tig * 2;
                const float vx = acc2[q][nt][eh * 2 + 0] + b2[n];
                const float vy = acc2[q][nt][eh * 2 + 1] + b2[n + 1];
                const int s = mm & 127, cch = (mm >> 7) & 31, hh = (mm >> 12) & 15, bb2 = mm >> 16;
                const size_t oidx = (((size_t)bb2 * T_) + cch * CS_ + s) * C_ + hh * D_ + n;
                *reinterpret_cast<uint32_t*>(obuf + oidx) = h2u(vx, vy);
            }
        }
    }
}

// ============================ converts ============================
__global__ __launch_bounds__(256)
void cvt_half_kernel(const float4* __restrict__ src, uint2* __restrict__ dst, int n4)
{
    const int i = blockIdx.x * blockDim.x + threadIdx.x;
    if (i >= n4) return;
    const float4 v = src[i];
    dst[i] = make_uint2(h2u(v.x, v.y), h2u(v.z, v.w));
}

__global__ void cvt_wt_kernel(const float* __restrict__ W, __half* __restrict__ Wt,
                              int Kd, int Nd)
{
    __shared__ float tile[32][33];
    const int k0 = blockIdx.y * 32, n0 = blockIdx.x * 32;
    const int tx = threadIdx.x, ty = threadIdx.y;
#pragma unroll
    for (int j = 0; j < 32; j += 8)
        tile[ty + j][tx] = W[(size_t)(k0 + ty + j) * Nd + n0 + tx];
    __syncthreads();
#pragma unroll
    for (int j = 0; j < 32; j += 8)
        Wt[(size_t)(n0 + ty + j) * Kd + k0 + tx] = __float2half_rn(tile[tx][ty + j]);
}

// ---------------- exclusive cross-chunk prefix of csum ----------------
__global__ void scan_csum_kernel(const float* __restrict__ csum, float* __restrict__ carry)
{
    const int bh = blockIdx.x, d = threadIdx.x;
    float run = 0.f;
    for (int ch = 0; ch < NC_; ch++) {
        const size_t i = (size_t)(bh * NC_ + ch) * 64 + d;
        carry[i] = run;
        run += csum[i];
    }
}

// ---------------- parallel LN of carries ----------------
__global__ __launch_bounds__(64)
void ln_carry_kernel(const float* __restrict__ carry,
                     const float* __restrict__ g, const float* __restrict__ bb,
                     float* __restrict__ ncar)
{
    const int r = blockIdx.x, d = threadIdx.x;
    const int lane = d & 31, w = d >> 5;
    __shared__ float sh[2];
    const float val = carry[(size_t)r * 64 + d];
    float s = warpSum(val);
    if (lane == 0) sh[w] = s;
    __syncthreads();
    const float mean = (sh[0] + sh[1]) * (1.f / 64.f);
    __syncthreads();
    const float df = val - mean;
    float s2 = warpSum(df * df);
    if (lane == 0) sh[w] = s2;
    __syncthreads();
    const float var = (sh[0] + sh[1]) * (1.f / 64.f);
    ncar[(size_t)r * 64 + d] = df * rsqrtf(var + EPS_) * g[d] + bb[d];
}

// ---------------- final LayerNorm over C + residual ----------------
__global__ __launch_bounds__(256)
void ln_res_kernel(const float* __restrict__ p, const float* __restrict__ x,
                   const float* __restrict__ g, const float* __restrict__ bb,
                   float* __restrict__ out)
{
    const int row = blockIdx.x;
    const int t   = threadIdx.x;
    const float4 lv = reinterpret_cast<const float4*>(p + (size_t)row * C_)[t];
    float s = lv.x + lv.y + lv.z + lv.w;
    __shared__ float red[8];
    s = warpSum(s);
    if ((t & 31) == 0) red[t >> 5] = s;
    __syncthreads();
    float tot = 0.f;
#pragma unroll
    for (int i = 0; i < 8; i++) tot += red[i];
    const float mean = tot * (1.f / 1024.f);
    __syncthreads();
    const float d0 = lv.x - mean, d1 = lv.y - mean, d2 = lv.z - mean, d3 = lv.w - mean;
    float sq = d0 * d0 + d1 * d1 + d2 * d2 + d3 * d3;
    sq = warpSum(sq);
    if ((t & 31) == 0) red[t >> 5] = sq;
    __syncthreads();
    float v2 = 0.f;
#pragma unroll
    for (int i = 0; i < 8; i++) v2 += red[i];
    const float rs = rsqrtf(v2 * (1.f / 1024.f) + EPS_);
    const float4 xv = reinterpret_cast<const float4*>(x + (size_t)row * C_)[t];
    const float4 gv = reinterpret_cast<const float4*>(g)[t];
    const float4 bv = reinterpret_cast<const float4*>(bb)[t];
    float4 o;
    o.x = xv.x + d0 * rs * gv.x + bv.x;
    o.y = xv.y + d1 * rs * gv.y + bv.y;
    o.z = xv.z + d2 * rs * gv.z + bv.z;
    o.w = xv.w + d3 * rs * gv.w + bv.w;
    reinterpret_cast<float4*>(out + (size_t)row * C_)[t] = o;
}

// ---------------- launch ----------------
extern "C" void kernel_launch(void* const* d_in, const int* in_sizes, int n_in,
                              void* d_out, int out_size)
{
    const float* x       = (const float*)d_in[0];
    const float* mark_W  = (const float*)d_in[1];
    const float* mark_b  = (const float*)d_in[2];
    const float* gate_W  = (const float*)d_in[3];
    const float* gate_b  = (const float*)d_in[4];
    const float* carry_g = (const float*)d_in[5];
    const float* carry_b = (const float*)d_in[6];
    const float* card_g  = (const float*)d_in[7];
    const float* card_b  = (const float*)d_in[8];
    const float* ho1_W   = (const float*)d_in[9];
    const float* ho1_b   = (const float*)d_in[10];
    const float* ho2_W   = (const float*)d_in[11];
    const float* ho2_b   = (const float*)d_in[12];
    const float* proj_W  = (const float*)d_in[13];
    const float* proj_b  = (const float*)d_in[14];
    const float* ln_g    = (const float*)d_in[15];
    const float* ln_b    = (const float*)d_in[16];
    float* out = (float*)d_out;

    static float *gmc = nullptr, *csum, *car, *ncar, *pbuf;
    static __half *pmh, *xh, *obuf, *wmT, *wgT, *wpT, *w1T, *w2T;
    if (!gmc) {
        cudaGetSymbolAddress((void**)&gmc,  g_gmc);
        cudaGetSymbolAddress((void**)&csum, g_csum);
        cudaGetSymbolAddress((void**)&car,  g_car);
        cudaGetSymbolAddress((void**)&ncar, g_ncar);
        cudaGetSymbolAddress((void**)&pbuf, g_pbuf);
        cudaGetSymbolAddress((void**)&pmh,  g_pmh);
        cudaGetSymbolAddress((void**)&xh,   g_xh);
        cudaGetSymbolAddress((void**)&obuf, g_obuf);
        cudaGetSymbolAddress((void**)&wmT,  g_wmT);
        cudaGetSymbolAddress((void**)&wgT,  g_wgT);
        cudaGetSymbolAddress((void**)&wpT,  g_wpT);
        cudaGetSymbolAddress((void**)&w1T,  g_w1T);
        cudaGetSymbolAddress((void**)&w2T,  g_w2T);
        cudaFuncSetAttribute(hgemm<0>, cudaFuncAttributeMaxDynamicSharedMemorySize, 147456);
        cudaFuncSetAttribute(hgemm<1>, cudaFuncAttributeMaxDynamicSharedMemorySize, 147456);
        cudaFuncSetAttribute(hgemm<2>, cudaFuncAttributeMaxDynamicSharedMemorySize, 147456);
        cudaFuncSetAttribute(scan_mlp, cudaFuncAttributeMaxDynamicSharedMemorySize, 115200);
    }

    const int M  = B_ * T_;              // 16384
    const int n4 = M * C_ / 4;

    // 1-3: prerequisites for mark GEMM
    cvt_half_kernel<<<(n4 + 255) / 256, 256>>>((const float4*)x, (uint2*)xh, n4);
    cvt_wt_kernel<<<dim3(32, 32), dim3(32, 8)>>>(mark_W, wmT, 1024, 1024);
    cvt_wt_kernel<<<dim3(32, 32), dim3(32, 8)>>>(gate_W, wgT, 1024, 1024);

    // 4: pm(half) = x @ mark_W + mark_b   (ncu profiles our launch #4)
    hgemm<2><<<dim3(4, 128), 512, 147456>>>(M, C_, C_, xh, wmT, mark_b,
                                            nullptr, pmh, nullptr, nullptr);
    // 5: gmc = sigmoid(x @ gate_W + gate_b) * pm, + csum
    hgemm<1><<<dim3(4, 128), 512, 147456>>>(M, C_, C_, xh, wgT, gate_b,
                                            nullptr, pmh, gmc, csum);

    // 6-8: remaining converts
    cvt_wt_kernel<<<dim3(32, 32), dim3(32, 8)>>>(proj_W, wpT, 1024, 1024);
    cvt_wt_kernel<<<dim3(4, 4),   dim3(32, 8)>>>(ho1_W,  w1T, 128, 128);
    cvt_wt_kernel<<<dim3(2, 4),   dim3(32, 8)>>>(ho2_W,  w2T, 128, 64);

    // 9-10: carry chain
    scan_csum_kernel<<<B_ * H_, 64>>>(csum, car);
    ln_carry_kernel<<<2048, 64>>>(car, carry_g, carry_b, ncar);

    // 11: fused scan + cards + MLP -> obuf
    scan_mlp<<<2048, 256, 115200>>>(gmc, x, ncar, card_g, card_b,
                                    w1T, w2T, ho1_b, ho2_b, obuf);

    // 12: proj
    hgemm<0><<<dim3(4, 128), 512, 147456>>>(M, C_, C_, obuf, wpT, proj_b,
                                            pbuf, nullptr, nullptr, nullptr);

    // 13: final LN + residual
    ln_res_kernel<<<M, 256>>>(pbuf, x, ln_g, ln_b, out);
}

// round 14
// speedup vs baseline: 1.8913x; 1.1368x over previous
#include <cuda_runtime.h>
#include <cuda_fp16.h>
#include <math.h>
#include <stdint.h>

#define B_   4
#define T_   4096
#define C_   1024
#define H_   16
#define CS_  128
#define D_   64
#define NC_  32
#define EPS_ 1e-5f

// ---------------- scratch (device globals; no allocations allowed) ----------------
__device__ __half g_pmh [(size_t)16384 * 1024];   // pm fp16
__device__ float  g_gmc [(size_t)262144 * 64];    // gm chunked [blk,s,d] fp32
__device__ float  g_csum[2048 * 64];
__device__ float  g_car [2048 * 64];
__device__ float  g_ncar[2048 * 64];
__device__ float  g_pbuf[(size_t)16384 * 1024];   // proj out pre-LN fp32
__device__ __half g_xh  [(size_t)16384 * 1024];   // x fp16
__device__ __half g_obuf[(size_t)16384 * 1024];   // mlp out scattered fp16
__device__ __half g_wmT [(size_t)1024 * 1024];    // W^T [N,K] fp16
__device__ __half g_wgT [(size_t)1024 * 1024];
__device__ __half g_wpT [(size_t)1024 * 1024];
__device__ __half g_w1T [128 * 128];
__device__ __half g_w2T [64 * 128];

__device__ __forceinline__ float warpSum(float v) {
#pragma unroll
    for (int o = 16; o > 0; o >>= 1) v += __shfl_xor_sync(0xffffffffu, v, o);
    return v;
}
__device__ __forceinline__ uint32_t smem_u32(const void* p) {
    uint32_t a;
    asm("{ .reg .u64 t; cvta.to.shared.u64 t, %1; cvt.u32.u64 %0, t; }" : "=r"(a) : "l"(p));
    return a;
}
__device__ __forceinline__ void cp16(uint32_t dst, const void* src) {
    asm volatile("cp.async.cg.shared.global [%0], [%1], 16;" :: "r"(dst), "l"(src));
}
#define LDSM4(r0, r1, r2, r3, addr) \
    asm volatile("ldmatrix.sync.aligned.m8n8.x4.shared.b16 {%0,%1,%2,%3}, [%4];" \
        : "=r"(r0), "=r"(r1), "=r"(r2), "=r"(r3) : "r"(addr))
__device__ __forceinline__ void mma_f16(float c[4],
                                        uint32_t a0, uint32_t a1, uint32_t a2, uint32_t a3,
                                        uint32_t b0, uint32_t b1) {
    asm volatile(
        "mma.sync.aligned.m16n8k16.row.col.f32.f16.f16.f32 "
        "{%0,%1,%2,%3}, {%4,%5,%6,%7}, {%8,%9}, {%0,%1,%2,%3};"
        : "+f"(c[0]), "+f"(c[1]), "+f"(c[2]), "+f"(c[3])
        : "r"(a0), "r"(a1), "r"(a2), "r"(a3), "r"(b0), "r"(b1));
}
__device__ __forceinline__ uint32_t h2u(float a, float b) {
    __half2 h = __floats2half2_rn(a, b);
    return *reinterpret_cast<uint32_t*>(&h);
}

// stage ROWS x 64-half tile (128B rows, XOR-granule swizzle) via cp.async; K in halfs
template <int ROWS, int NTH>
__device__ __forceinline__ void stage_tile_h(uint32_t sdst, const __half* __restrict__ gsrc,
                                             int K, int tid) {
#pragma unroll
    for (int i = 0; i < ROWS * 8 / NTH; i++) {
        const int c = i * NTH + tid;
        const int m = c >> 3, g4 = c & 7;
        cp16(sdst + (uint32_t)(m * 128 + ((g4 ^ (m & 7)) << 4)),
             gsrc + (size_t)m * K + g4 * 8);
    }
}

// ============ FP16 GEMM: 128x128x64 CTA tile, 256 thr, 2 CTAs/SM, 3-stage ============
// Warp grid 4(M) x 2(N), warp tile 32x64 (acc 64 regs).
// EPI 0: Cf(fp32) = acc+bias.   EPI 2: Ch(fp16) = acc+bias.
// EPI 1: C2(fp32 chunked) = sigmoid(acc+bias)*Ch(pm fp16); + per-chunk csum slice.
template <int EPI>
__global__ __launch_bounds__(256, 2)
void hgemm(int M, int N, int K,
           const __half* __restrict__ A,
           const __half* __restrict__ Bt,
           const float* __restrict__ bias,
           float* __restrict__ Cf,
           __half* __restrict__ Ch,
           float* __restrict__ C2,
           float* __restrict__ csum)
{
    constexpr int NT2 = 8, NPAIR = 4;          // warp N = 64
    constexpr int STG = 32 * 1024;             // A 16KB + B 16KB per stage

    extern __shared__ char smem[];
    const uint32_t sb = smem_u32(smem);

    const int tid = threadIdx.x, wid = tid >> 5, lane = tid & 31;
    const int wy = wid >> 1, wx = wid & 1;     // 4 x 2
    const int gid = lane >> 2, tig = lane & 3;
    const int lrow = lane & 15, lgh = lane >> 4;

    const int crow = blockIdx.y * 128, ccol = blockIdx.x * 128;
    const __half* Ag = A + (size_t)crow * K;
    const __half* Bg = Bt + (size_t)ccol * K;

    float acc[2][NT2][4];
#pragma unroll
    for (int q = 0; q < 2; q++)
#pragma unroll
        for (int nt = 0; nt < NT2; nt++)
#pragma unroll
            for (int e = 0; e < 4; e++) acc[q][nt][e] = 0.f;

    const int nT = K / 64;

#pragma unroll
    for (int s = 0; s < 2; s++) {
        stage_tile_h<128, 256>(sb + s * STG, Ag + s * 64, K, tid);
        stage_tile_h<128, 256>(sb + s * STG + 16384, Bg + s * 64, K, tid);
        asm volatile("cp.async.commit_group;");
    }

    for (int t = 0; t < nT; t++) {
        if (t < nT - 1) asm volatile("cp.async.wait_group 1;" ::: "memory");
        else            asm volatile("cp.async.wait_group 0;" ::: "memory");
        __syncthreads();
        if (t + 2 < nT) {
            const int slot = (t + 2) % 3;
            stage_tile_h<128, 256>(sb + slot * STG, Ag + (t + 2) * 64, K, tid);
            stage_tile_h<128, 256>(sb + slot * STG + 16384, Bg + (t + 2) * 64, K, tid);
            asm volatile("cp.async.commit_group;");
        }
        const uint32_t aBase = sb + (t % 3) * STG;
        const uint32_t bBase = aBase + 16384;
#pragma unroll
        for (int kk2 = 0; kk2 < 8; kk2 += 2) {     // one k16 mma step per iteration
            uint32_t a[2][4];
#pragma unroll
            for (int q = 0; q < 2; q++) {
                const int row = wy * 32 + q * 16 + lrow;
                LDSM4(a[q][0], a[q][1], a[q][2], a[q][3],
                      aBase + row * 128 + (((kk2 + lgh) ^ (row & 7)) << 4));
            }
            uint32_t bfr[NT2][2];
#pragma unroll
            for (int p = 0; p < NPAIR; p++) {
                const int row = wx * 64 + p * 16 + lrow;
                uint32_t r0, r1, r2, r3;
                LDSM4(r0, r1, r2, r3, bBase + row * 128 + (((kk2 + lgh) ^ (row & 7)) << 4));
                bfr[2 * p][0] = r0; bfr[2 * p + 1][0] = r1;
                bfr[2 * p][1] = r2; bfr[2 * p + 1][1] = r3;
            }
#pragma unroll
            for (int q = 0; q < 2; q++)
#pragma unroll
                for (int nt = 0; nt < NT2; nt++)
                    mma_f16(acc[q][nt], a[q][0], a[q][1], a[q][2], a[q][3],
                            bfr[nt][0], bfr[nt][1]);
        }
    }

    float colsum[NT2][2];
    if (EPI == 1) {
#pragma unroll
        for (int nt = 0; nt < NT2; nt++) { colsum[nt][0] = 0.f; colsum[nt][1] = 0.f; }
    }

#pragma unroll
    for (int q = 0; q < 2; q++) {
#pragma unroll
        for (int nt = 0; nt < NT2; nt++) {
#pragma unroll
            for (int eh = 0; eh < 2; eh++) {
                const int m = crow + wy * 32 + q * 16 + gid + eh * 8;
                const int n = ccol + wx * 64 + nt * 8 + tig * 2;
                float2 v;
                v.x = acc[q][nt][eh * 2 + 0] + bias[n];
                v.y = acc[q][nt][eh * 2 + 1] + bias[n + 1];
                if (EPI == 1) {
                    const uint32_t ou = *reinterpret_cast<const uint32_t*>(Ch + (size_t)m * N + n);
                    const float2 old = __half22float2(*reinterpret_cast<const __half2*>(&ou));
                    v.x = old.x / (1.f + __expf(-v.x));
                    v.y = old.y / (1.f + __expf(-v.y));
                    colsum[nt][0] += v.x;
                    colsum[nt][1] += v.y;
                    const int s = m & 127, ch = (m >> 7) & 31, h = n >> 6, b = m >> 12;
                    const int d = n & 63;
                    const size_t idx = ((((size_t)(b * 16 + h) * 32 + ch) * 128 + s) * 64) + d;
                    *reinterpret_cast<float2*>(C2 + idx) = v;
                } else if (EPI == 2) {
                    *reinterpret_cast<uint32_t*>(Ch + (size_t)m * N + n) = h2u(v.x, v.y);
                } else {
                    *reinterpret_cast<float2*>(Cf + (size_t)m * N + n) = v;
                }
            }
        }
    }

    if (EPI == 1) {
        // per-chunk column sums over this CTA's 128 rows x 128 cols
        __syncthreads();
        float* cs = reinterpret_cast<float*>(smem);
        if (tid < 128) cs[tid] = 0.f;
        __syncthreads();
#pragma unroll
        for (int nt = 0; nt < NT2; nt++) {
            float s0 = colsum[nt][0], s1 = colsum[nt][1];
            s0 += __shfl_xor_sync(0xffffffffu, s0, 4);
            s0 += __shfl_xor_sync(0xffffffffu, s0, 8);
            s0 += __shfl_xor_sync(0xffffffffu, s0, 16);
            s1 += __shfl_xor_sync(0xffffffffu, s1, 4);
            s1 += __shfl_xor_sync(0xffffffffu, s1, 8);
            s1 += __shfl_xor_sync(0xffffffffu, s1, 16);
            if (gid == 0) {
                atomicAdd(&cs[wx * 64 + nt * 8 + tig * 2 + 0], s0);
                atomicAdd(&cs[wx * 64 + nt * 8 + tig * 2 + 1], s1);
            }
        }
        __syncthreads();
        if (tid < 128) {
            const int n = ccol + tid, h = n >> 6, d = n & 63;
            const int b = crow >> 12, ch = (crow >> 7) & 31;
            csum[(size_t)((b * 16 + h) * 32 + ch) * 64 + d] = cs[tid];
        }
    }
}

// ============ fused: chunk scan + cards LN + comb(in smem) + MLP -> obuf ============
__global__ __launch_bounds__(256)
void scan_mlp(const float* __restrict__ gmc,
              const float* __restrict__ x,
              const float* __restrict__ ncar,
              const float* __restrict__ cg, const float* __restrict__ cb,
              const __half* __restrict__ w1T, const __half* __restrict__ w2T,
              const float* __restrict__ b1, const float* __restrict__ b2,
              __half* __restrict__ obuf)
{
    extern __shared__ char smem[];
    const uint32_t sb  = smem_u32(smem);
    const uint32_t sW1 = sb;                  // 32768
    const uint32_t sW2 = sb + 32768;          // 16384
    const uint32_t sA  = sb + 49152;          // 32768 (comb fp16, 2 kt chunks)
    const uint32_t sH  = sb + 81920;          // 33280 scan buffer; reused as h tiles
    float* gm = reinterpret_cast<float*>(smem + 81920);

    const int tid = threadIdx.x, wid = tid >> 5, lane = tid & 31;
    const int wy = wid >> 2, wx = wid & 3;
    const int gid = lane >> 2, tig = lane & 3;
    const int lrow = lane & 15, lgh = lane >> 4;
    const int blk = blockIdx.x;
    const int ch = blk % NC_, h = (blk / NC_) % H_, b = blk / (NC_ * H_);

    __shared__ float ncs[D_], gs[D_], bs[D_];

#pragma unroll
    for (int i = 0; i < 8; i++) {
        const int c = i * 256 + tid;
        const int kt = c >> 10, rem = c & 1023, n = rem >> 3, g4 = rem & 7;
        cp16(sW1 + kt * 16384 + n * 128 + ((g4 ^ (n & 7)) << 4),
             w1T + (size_t)n * 128 + kt * 64 + g4 * 8);
    }
#pragma unroll
    for (int i = 0; i < 4; i++) {
        const int c = i * 256 + tid;
        const int kt = c >> 9, rem = c & 511, n = rem >> 3, g4 = rem & 7;
        cp16(sW2 + kt * 8192 + n * 128 + ((g4 ^ (n & 7)) << 4),
             w2T + (size_t)n * 128 + kt * 64 + g4 * 8);
    }
    asm volatile("cp.async.commit_group;");

    const float4* src = reinterpret_cast<const float4*>(gmc + (size_t)blk * CS_ * D_);
#pragma unroll
    for (int i = 0; i < 8; i++) {
        const int e = tid + i * 256;
        const int s = e >> 4, d4 = (e & 15) * 4;
        const float4 t = src[e];
        float* p = &gm[s * 65 + d4];
        p[0] = t.x; p[1] = t.y; p[2] = t.z; p[3] = t.w;
    }
    if (tid < D_) { ncs[tid] = ncar[(size_t)blk * D_ + tid]; gs[tid] = cg[tid]; bs[tid] = cb[tid]; }
    __syncthreads();

    if (tid < D_) {
        float acc = 0.f;
#pragma unroll 4
        for (int s = 0; s < CS_; s++) { acc += gm[s * 65 + tid]; gm[s * 65 + tid] = acc; }
    }
    __syncthreads();

    if (tid < 128) {
        const int s = tid;
        float v[D_];
        if (s == 0) {
#pragma unroll
            for (int d = 0; d < D_; d++) v[d] = ncs[d];
        } else {
            const float* row = &gm[(s - 1) * 65];
#pragma unroll
            for (int d = 0; d < D_; d++) v[d] = row[d] + ncs[d];
        }
        float sum = 0.f;
#pragma unroll
        for (int d = 0; d < D_; d++) sum += v[d];
        const float mean = sum * (1.f / 64.f);
        float sq = 0.f;
#pragma unroll
        for (int d = 0; d < D_; d++) { const float df = v[d] - mean; sq += df * df; }
        const float rs = rsqrtf(sq * (1.f / 64.f) + EPS_);

        const uint32_t rowbase0 = sA + s * 128;
        const uint32_t rowbase1 = sA + 16384 + s * 128;
        const float4* xr = reinterpret_cast<const float4*>(
            x + (((size_t)b * T_) + ch * CS_ + s) * C_ + h * D_);
#pragma unroll
        for (int i = 0; i < 16; i++) {
            const float4 t = xr[i];
            const int d = 4 * i, g4 = d >> 3;
            const uint32_t ad = rowbase0 + ((g4 ^ (s & 7)) << 4) + (d & 7) * 2;
            const uint32_t u0 = h2u(t.x, t.y), u1 = h2u(t.z, t.w);
            asm volatile("st.shared.u32 [%0], %1;" :: "r"(ad), "r"(u0));
            asm volatile("st.shared.u32 [%0], %1;" :: "r"(ad + 4), "r"(u1));
        }
#pragma unroll
        for (int i = 0; i < 32; i++) {
            const float a = (v[2 * i + 0] - mean) * rs * gs[2 * i + 0] + bs[2 * i + 0];
            const float c = (v[2 * i + 1] - mean) * rs * gs[2 * i + 1] + bs[2 * i + 1];
            const int d = 2 * i, g4 = d >> 3;
            const uint32_t ad = rowbase1 + ((g4 ^ (s & 7)) << 4) + (d & 7) * 2;
            const uint32_t u = h2u(a, c);
            asm volatile("st.shared.u32 [%0], %1;" :: "r"(ad), "r"(u));
        }
    }
    asm volatile("cp.async.wait_group 0;" ::: "memory");
    __syncthreads();

    float acc1[4][4][4];
#pragma unroll
    for (int q = 0; q < 4; q++)
#pragma unroll
        for (int nt = 0; nt < 4; nt++)
#pragma unroll
            for (int e = 0; e < 4; e++) acc1[q][nt][e] = 0.f;

#pragma unroll
    for (int kt = 0; kt < 2; kt++) {
        const uint32_t aBase = sA + kt * 16384;
        const uint32_t bBase = sW1 + kt * 16384;
#pragma unroll
        for (int kk2 = 0; kk2 < 8; kk2 += 2) {
            uint32_t a[4][4];
#pragma unroll
            for (int q = 0; q < 4; q++) {
                const int row = wy * 64 + q * 16 + lrow;
                LDSM4(a[q][0], a[q][1], a[q][2], a[q][3],
                      aBase + row * 128 + (((kk2 + lgh) ^ (row & 7)) << 4));
            }
            uint32_t bfr[4][2];
#pragma unroll
            for (int p = 0; p < 2; p++) {
                const int row = wx * 32 + p * 16 + lrow;
                uint32_t r0, r1, r2, r3;
                LDSM4(r0, r1, r2, r3, bBase + row * 128 + (((kk2 + lgh) ^ (row & 7)) << 4));
                bfr[2 * p][0] = r0; bfr[2 * p + 1][0] = r1;
                bfr[2 * p][1] = r2; bfr[2 * p + 1][1] = r3;
            }
#pragma unroll
            for (int q = 0; q < 4; q++)
#pragma unroll
                for (int nt = 0; nt < 4; nt++)
                    mma_f16(acc1[q][nt], a[q][0], a[q][1], a[q][2], a[q][3],
                            bfr[nt][0], bfr[nt][1]);
        }
    }
    __syncthreads();

#pragma unroll
    for (int q = 0; q < 4; q++) {
#pragma unroll
        for (int nt = 0; nt < 4; nt++) {
#pragma unroll
            for (int eh = 0; eh < 2; eh++) {
                const int m = wy * 64 + q * 16 + gid + eh * 8;
                const int n = wx * 32 + nt * 8 + tig * 2;
                float vx = acc1[q][nt][eh * 2 + 0] + b1[n];
                float vy = acc1[q][nt][eh * 2 + 1] + b1[n + 1];
                vx = 0.5f * vx * (1.f + erff(vx * 0.70710678118654752440f));
                vy = 0.5f * vy * (1.f + erff(vy * 0.70710678118654752440f));
                const int kt = n >> 6, g4 = (n & 63) >> 3;
                const uint32_t ad = sH + kt * 16384 + m * 128 +
                                    ((g4 ^ (m & 7)) << 4) + (n & 7) * 2;
                const uint32_t hv = h2u(vx, vy);
                asm volatile("st.shared.u32 [%0], %1;" :: "r"(ad), "r"(hv));
            }
        }
    }
    __syncthreads();

    float acc2[4][2][4];
#pragma unroll
    for (int q = 0; q < 4; q++)
#pragma unroll
        for (int nt = 0; nt < 2; nt++)
#pragma unroll
            for (int e = 0; e < 4; e++) acc2[q][nt][e] = 0.f;

#pragma unroll
    for (int kt = 0; kt < 2; kt++) {
        const uint32_t aBase = sH + kt * 16384;
        const uint32_t bBase = sW2 + kt * 8192;
#pragma unroll
        for (int kk2 = 0; kk2 < 8; kk2 += 2) {
            uint32_t a[4][4];
#pragma unroll
            for (int q = 0; q < 4; q++) {
                const int row = wy * 64 + q * 16 + lrow;
                LDSM4(a[q][0], a[q][1], a[q][2], a[q][3],
                      aBase + row * 128 + (((kk2 + lgh) ^ (row & 7)) << 4));
            }
            uint32_t bfr[2][2];
            {
                const int row = wx * 16 + lrow;
                uint32_t r0, r1, r2, r3;
                LDSM4(r0, r1, r2, r3, bBase + row * 128 + (((kk2 + lgh) ^ (row & 7)) << 4));
                bfr[0][0] = r0; bfr[1][0] = r1; bfr[0][1] = r2; bfr[1][1] = r3;
            }
#pragma unroll
            for (int q = 0; q < 4; q++)
#pragma unroll
                for (int nt = 0; nt < 2; nt++)
                    mma_f16(acc2[q][nt], a[q][0], a[q][1], a[q][2], a[q][3],
                            bfr[nt][0], bfr[nt][1]);
        }
    }

#pragma unroll
    for (int q = 0; q < 4; q++) {
#pragma unroll
        for (int nt = 0; nt < 2; nt++) {
#pragma unroll
            for (int eh = 0; eh < 2; eh++) {
                const int mm = blk * 128 + wy * 64 + q * 16 + gid + eh * 8;
                const int n = wx * 16 + nt * 8 + tig * 2;
                const float vx = acc2[q][nt][eh * 2 + 0] + b2[n];
                const float vy = acc2[q][nt][eh * 2 + 1] + b2[n + 1];
                const int s = mm & 127, cch = (mm >> 7) & 31, hh = (mm >> 12) & 15, bb2 = mm >> 16;
                const size_t oidx = (((size_t)bb2 * T_) + cch * CS_ + s) * C_ + hh * D_ + n;
                *reinterpret_cast<uint32_t*>(obuf + oidx) = h2u(vx, vy);
            }
        }
    }
}

// ============================ converts ============================
__global__ __launch_bounds__(256)
void cvt_half_kernel(const float4* __restrict__ src, uint2* __restrict__ dst, int n4)
{
    const int i = blockIdx.x * blockDim.x + threadIdx.x;
    if (i >= n4) return;
    const float4 v = src[i];
    dst[i] = make_uint2(h2u(v.x, v.y), h2u(v.z, v.w));
}

__global__ void cvt_wt_kernel(const float* __restrict__ W, __half* __restrict__ Wt,
                              int Kd, int Nd)
{
    __shared__ float tile[32][33];
    const int k0 = blockIdx.y * 32, n0 = blockIdx.x * 32;
    const int tx = threadIdx.x, ty = threadIdx.y;
#pragma unroll
    for (int j = 0; j < 32; j += 8)
        tile[ty + j][tx] = W[(size_t)(k0 + ty + j) * Nd + n0 + tx];
    __syncthreads();
#pragma unroll
    for (int j = 0; j < 32; j += 8)
        Wt[(size_t)(n0 + ty + j) * Kd + k0 + tx] = __float2half_rn(tile[tx][ty + j]);
}

// ---------------- exclusive cross-chunk prefix of csum ----------------
__global__ void scan_csum_kernel(const float* __restrict__ csum, float* __restrict__ carry)
{
    const int bh = blockIdx.x, d = threadIdx.x;
    float run = 0.f;
    for (int ch = 0; ch < NC_; ch++) {
        const size_t i = (size_t)(bh * NC_ + ch) * 64 + d;
        carry[i] = run;
        run += csum[i];
    }
}

// ---------------- parallel LN of carries ----------------
__global__ __launch_bounds__(64)
void ln_carry_kernel(const float* __restrict__ carry,
                     const float* __restrict__ g, const float* __restrict__ bb,
                     float* __restrict__ ncar)
{
    const int r = blockIdx.x, d = threadIdx.x;
    const int lane = d & 31, w = d >> 5;
    __shared__ float sh[2];
    const float val = carry[(size_t)r * 64 + d];
    float s = warpSum(val);
    if (lane == 0) sh[w] = s;
    __syncthreads();
    const float mean = (sh[0] + sh[1]) * (1.f / 64.f);
    __syncthreads();
    const float df = val - mean;
    float s2 = warpSum(df * df);
    if (lane == 0) sh[w] = s2;
    __syncthreads();
    const float var = (sh[0] + sh[1]) * (1.f / 64.f);
    ncar[(size_t)r * 64 + d] = df * rsqrtf(var + EPS_) * g[d] + bb[d];
}

// ---------------- final LayerNorm over C + residual ----------------
__global__ __launch_bounds__(256)
void ln_res_kernel(const float* __restrict__ p, const float* __restrict__ x,
                   const float* __restrict__ g, const float* __restrict__ bb,
                   float* __restrict__ out)
{
    const int row = blockIdx.x;
    const int t   = threadIdx.x;
    const float4 lv = reinterpret_cast<const float4*>(p + (size_t)row * C_)[t];
    float s = lv.x + lv.y + lv.z + lv.w;
    __shared__ float red[8];
    s = warpSum(s);
    if ((t & 31) == 0) red[t >> 5] = s;
    __syncthreads();
    float tot = 0.f;
#pragma unroll
    for (int i = 0; i < 8; i++) tot += red[i];
    const float mean = tot * (1.f / 1024.f);
    __syncthreads();
    const float d0 = lv.x - mean, d1 = lv.y - mean, d2 = lv.z - mean, d3 = lv.w - mean;
    float sq = d0 * d0 + d1 * d1 + d2 * d2 + d3 * d3;
    sq = warpSum(sq);
    if ((t & 31) == 0) red[t >> 5] = sq;
    __syncthreads();
    float v2 = 0.f;
#pragma unroll
    for (int i = 0; i < 8; i++) v2 += red[i];
    const float rs = rsqrtf(v2 * (1.f / 1024.f) + EPS_);
    const float4 xv = reinterpret_cast<const float4*>(x + (size_t)row * C_)[t];
    const float4 gv = reinterpret_cast<const float4*>(g)[t];
    const float4 bv = reinterpret_cast<const float4*>(bb)[t];
    float4 o;
    o.x = xv.x + d0 * rs * gv.x + bv.x;
    o.y = xv.y + d1 * rs * gv.y + bv.y;
    o.z = xv.z + d2 * rs * gv.z + bv.z;
    o.w = xv.w + d3 * rs * gv.w + bv.w;
    reinterpret_cast<float4*>(out + (size_t)row * C_)[t] = o;
}

// ---------------- launch ----------------
extern "C" void kernel_launch(void* const* d_in, const int* in_sizes, int n_in,
                              void* d_out, int out_size)
{
    const float* x       = (const float*)d_in[0];
    const float* mark_W  = (const float*)d_in[1];
    const float* mark_b  = (const float*)d_in[2];
    const float* gate_W  = (const float*)d_in[3];
    const float* gate_b  = (const float*)d_in[4];
    const float* carry_g = (const float*)d_in[5];
    const float* carry_b = (const float*)d_in[6];
    const float* card_g  = (const float*)d_in[7];
    const float* card_b  = (const float*)d_in[8];
    const float* ho1_W   = (const float*)d_in[9];
    const float* ho1_b   = (const float*)d_in[10];
    const float* ho2_W   = (const float*)d_in[11];
    const float* ho2_b   = (const float*)d_in[12];
    const float* proj_W  = (const float*)d_in[13];
    const float* proj_b  = (const float*)d_in[14];
    const float* ln_g    = (const float*)d_in[15];
    const float* ln_b    = (const float*)d_in[16];
    float* out = (float*)d_out;

    static float *gmc = nullptr, *csum, *car, *ncar, *pbuf;
    static __half *pmh, *xh, *obuf, *wmT, *wgT, *wpT, *w1T, *w2T;
    if (!gmc) {
        cudaGetSymbolAddress((void**)&gmc,  g_gmc);
        cudaGetSymbolAddress((void**)&csum, g_csum);
        cudaGetSymbolAddress((void**)&car,  g_car);
        cudaGetSymbolAddress((void**)&ncar, g_ncar);
        cudaGetSymbolAddress((void**)&pbuf, g_pbuf);
        cudaGetSymbolAddress((void**)&pmh,  g_pmh);
        cudaGetSymbolAddress((void**)&xh,   g_xh);
        cudaGetSymbolAddress((void**)&obuf, g_obuf);
        cudaGetSymbolAddress((void**)&wmT,  g_wmT);
        cudaGetSymbolAddress((void**)&wgT,  g_wgT);
        cudaGetSymbolAddress((void**)&wpT,  g_wpT);
        cudaGetSymbolAddress((void**)&w1T,  g_w1T);
        cudaGetSymbolAddress((void**)&w2T,  g_w2T);
        cudaFuncSetAttribute(hgemm<0>, cudaFuncAttributeMaxDynamicSharedMemorySize, 98304);
        cudaFuncSetAttribute(hgemm<1>, cudaFuncAttributeMaxDynamicSharedMemorySize, 98304);
        cudaFuncSetAttribute(hgemm<2>, cudaFuncAttributeMaxDynamicSharedMemorySize, 98304);
        cudaFuncSetAttribute(scan_mlp, cudaFuncAttributeMaxDynamicSharedMemorySize, 115200);
    }

    const int M  = B_ * T_;              // 16384
    const int n4 = M * C_ / 4;

    // 1-3: prerequisites for mark GEMM
    cvt_half_kernel<<<(n4 + 255) / 256, 256>>>((const float4*)x, (uint2*)xh, n4);
    cvt_wt_kernel<<<dim3(32, 32), dim3(32, 8)>>>(mark_W, wmT, 1024, 1024);
    cvt_wt_kernel<<<dim3(32, 32), dim3(32, 8)>>>(gate_W, wgT, 1024, 1024);

    // 4: pm(half) = x @ mark_W + mark_b   (ncu profiles our launch #4)
    hgemm<2><<<dim3(8, 128), 256, 98304>>>(M, C_, C_, xh, wmT, mark_b,
                                           nullptr, pmh, nullptr, nullptr);
    // 5: gmc = sigmoid(x @ gate_W + gate_b) * pm, + csum
    hgemm<1><<<dim3(8, 128), 256, 98304>>>(M, C_, C_, xh, wgT, gate_b,
                                           nullptr, pmh, gmc, csum);

    // 6-8: remaining converts
    cvt_wt_kernel<<<dim3(32, 32), dim3(32, 8)>>>(proj_W, wpT, 1024, 1024);
    cvt_wt_kernel<<<dim3(4, 4),   dim3(32, 8)>>>(ho1_W,  w1T, 128, 128);
    cvt_wt_kernel<<<dim3(2, 4),   dim3(32, 8)>>>(ho2_W,  w2T, 128, 64);

    // 9-10: carry chain
    scan_csum_kernel<<<B_ * H_, 64>>>(csum, car);
    ln_carry_kernel<<<2048, 64>>>(car, carry_g, carry_b, ncar);

    // 11: fused scan + cards + MLP -> obuf
    scan_mlp<<<2048, 256, 115200>>>(gmc, x, ncar, card_g, card_b,
                                    w1T, w2T, ho1_b, ho2_b, obuf);

    // 12: proj
    hgemm<0><<<dim3(8, 128), 256, 98304>>>(M, C_, C_, obuf, wpT, proj_b,
                                           pbuf, nullptr, nullptr, nullptr);

    // 13: final LN + residual
    ln_res_kernel<<<M, 256>>>(pbuf, x, ln_g, ln_b, out);
}